// round 12
// baseline (speedup 1.0000x reference)
#include <cuda_runtime.h>
#include <cuda_fp16.h>
#include <cstdint>
#include <cstdio>

#define NTOK   343
#define NWIN   256
#define NHEADS 12
#define HDIM   32
#define CDIM   384
#define MROWS  (NWIN * NTOK)     // 87808
#define QKVC   (3 * CDIM)        // 1152
#define NPAD   384
#define KPAD   384

// ---------------- scratch (static device globals) ---------------------------
__device__ __half g_qkv[(size_t)MROWS * QKVC];     // normal layout (attn input)
__device__ __half g_att[(size_t)MROWS * CDIM];     // chunk-major swizzled (proj A)
__device__ __half g_biasH[NHEADS * NPAD * KPAD];
__device__ __half g_xh[(size_t)MROWS * CDIM];      // chunk-major swizzled (qkv A)
__device__ __half g_wqt[(size_t)QKVC * CDIM];      // chunk-major swizzled (qkv B)
__device__ __half g_wpt[(size_t)CDIM * CDIM];      // chunk-major swizzled (proj B)

template<int N> struct IC { static constexpr int value = N; };

// ======================= helpers ============================================
__device__ __forceinline__ uint32_t smem_u32(const void* p) {
    uint32_t a;
    asm("{ .reg .u64 t; cvta.to.shared.u64 t, %1; cvt.u32.u64 %0, t; }" : "=r"(a) : "l"(p));
    return a;
}
__device__ __forceinline__ uint32_t pack_h2(float lo, float hi) {
    uint32_t r;
    asm("cvt.rn.f16x2.f32 %0, %1, %2;" : "=r"(r) : "f"(hi), "f"(lo));
    return r;
}
__device__ __forceinline__ void ldsm_x4(uint32_t& r0, uint32_t& r1, uint32_t& r2,
                                        uint32_t& r3, uint32_t addr) {
    asm volatile("ldmatrix.sync.aligned.m8n8.x4.shared.b16 {%0,%1,%2,%3}, [%4];"
                 : "=r"(r0), "=r"(r1), "=r"(r2), "=r"(r3) : "r"(addr));
}
__device__ __forceinline__ void ldsm_x4_t(uint32_t& r0, uint32_t& r1, uint32_t& r2,
                                          uint32_t& r3, uint32_t addr) {
    asm volatile("ldmatrix.sync.aligned.m8n8.x4.trans.shared.b16 {%0,%1,%2,%3}, [%4];"
                 : "=r"(r0), "=r"(r1), "=r"(r2), "=r"(r3) : "r"(addr));
}
#define CP_ASYNC16P(dst, src, n) \
    asm volatile("cp.async.cg.shared.global [%0], [%1], 16, %2;" :: "r"(dst), "l"(src), "r"(n))
#define CP_COMMIT() asm volatile("cp.async.commit_group;" ::: "memory")
#define CP_WAIT1()  asm volatile("cp.async.wait_group 1;" ::: "memory")
#define CP_WAIT0()  asm volatile("cp.async.wait_group 0;" ::: "memory")

#define MBARRIER_INIT(mb, cnt) \
    asm volatile("mbarrier.init.shared.b64 [%0], %1;" :: "r"((uint32_t)(mb)), "r"((uint32_t)(cnt)) : "memory")
#define MBARRIER_EXPECT_TX(mb, bytes) \
    asm volatile("mbarrier.arrive.expect_tx.shared.b64 _, [%0], %1;" :: "r"((uint32_t)(mb)), "r"((uint32_t)(bytes)) : "memory")
#define CP_BULK(dst, src, bytes, mb) \
    asm volatile("cp.async.bulk.shared::cluster.global.mbarrier::complete_tx::bytes [%0], [%1], %2, [%3];" \
                 :: "r"((uint32_t)(dst)), "l"(src), "r"((uint32_t)(bytes)), "r"((uint32_t)(mb)) : "memory")
#define MBARRIER_WAIT_PARITY(mb, ph) do {                                         \
    uint32_t _mb = (uint32_t)(mb); uint32_t _p = (uint32_t)(ph); uint32_t _done;  \
    asm volatile("{\n\t.reg .pred p;\n\t"                                         \
        "mbarrier.try_wait.parity.acquire.cta.shared::cta.b64 p, [%1], %2;\n\t"   \
        "selp.b32 %0, 1, 0, p;\n\t}" : "=r"(_done) : "r"(_mb), "r"(_p) : "memory"); \
    if (!_done) {                                                                 \
        asm volatile("{\n\t.reg .pred P1;\n\t"                                    \
            "WL_%=:\n\t"                                                          \
            "mbarrier.try_wait.parity.acquire.cta.shared::cta.b64 P1, [%0], %1, 0x989680;\n\t" \
            "@P1 bra.uni WD_%=;\n\t"                                              \
            "bra.uni WL_%=;\n\t"                                                  \
            "WD_%=:\n\t}" :: "r"(_mb), "r"(_p) : "memory");                       \
    }                                                                             \
} while (0)

__device__ __forceinline__ void mma_f16(float* c, const uint32_t* a, const uint32_t* b) {
    asm volatile(
        "mma.sync.aligned.m16n8k16.row.col.f32.f16.f16.f32 "
        "{%0,%1,%2,%3}, {%4,%5,%6,%7}, {%8,%9}, {%0,%1,%2,%3};"
        : "+f"(c[0]), "+f"(c[1]), "+f"(c[2]), "+f"(c[3])
        : "r"(a[0]), "r"(a[1]), "r"(a[2]), "r"(a[3]), "r"(b[0]), "r"(b[1]));
}

// ======================= fused prep kernel ==================================
#define NBX  16464
#define NBB  6912
#define NBTQ 432
#define NBTP 144
#define PREP_BLOCKS (NBX + NBB + NBTQ + NBTP)

__global__ __launch_bounds__(256) void prep_kernel(
    const float* __restrict__ x, const float* __restrict__ qkv_w,
    const float* __restrict__ proj_w, const float* __restrict__ bt,
    const int* __restrict__ ridx,
    __half* __restrict__ xh, __half* __restrict__ wqt,
    __half* __restrict__ wpt, __half* __restrict__ bf)
{
    __shared__ float t[32][33];
    const int bid = blockIdx.x;
    const int tid = threadIdx.x;

    if (bid < NBX) {
        size_t e = ((size_t)bid * 256 + tid) * 8;
        int row = (int)(e / CDIM);
        int hcf = (int)(e % CDIM);
        int c   = hcf >> 6;
        int grp = (hcf & 63) >> 3;
        float4 v0 = *reinterpret_cast<const float4*>(x + e);
        float4 v1 = *reinterpret_cast<const float4*>(x + e + 4);
        uint4 o;
        o.x = pack_h2(v0.x, v0.y); o.y = pack_h2(v0.z, v0.w);
        o.z = pack_h2(v1.x, v1.y); o.w = pack_h2(v1.z, v1.w);
        size_t dst = ((size_t)c * MROWS + row) * 64 + ((grp ^ (row & 7)) << 3);
        *reinterpret_cast<uint4*>(xh + dst) = o;
        return;
    }
    if (bid < NBX + NBB) {
        int idx = (bid - NBX) * 256 + tid;
        int h   = idx / (NPAD * KPAD);
        int rem = idx - h * NPAD * KPAD;
        int r   = rem / KPAD;
        int k   = rem - r * KPAD;
        float v;
        if (k >= NTOK)      v = -60000.f;
        else if (r >= NTOK) v = 0.f;
        else                v = bt[ridx[r * NTOK + k] * NHEADS + h];
        bf[idx] = __float2half(v);
        return;
    }
    const int tx = tid & 31, ty = tid >> 5;
    const float* W; __half* Wt; int Nw, bx, by;
    if (bid < NBX + NBB + NBTQ) {
        int bb = bid - NBX - NBB;
        W = qkv_w; Wt = wqt; Nw = QKVC;
        bx = bb % (QKVC / 32); by = bb / (QKVC / 32);
    } else {
        int bb = bid - NBX - NBB - NBTQ;
        W = proj_w; Wt = wpt; Nw = CDIM;
        bx = bb % (CDIM / 32); by = bb / (CDIM / 32);
    }
    int n0 = bx * 32, k0 = by * 32;
#pragma unroll
    for (int s = 0; s < 4; ++s) {
        int k = k0 + ty + s * 8;
        t[ty + s * 8][tx] = W[(size_t)k * Nw + n0 + tx];
    }
    __syncthreads();
#pragma unroll
    for (int s = 0; s < 4; ++s) {
        int n = n0 + ty + s * 8;
        int k = k0 + tx;
        int c = k >> 6, hc = k & 63;
        size_t dst = ((size_t)c * Nw + n) * 64
                     + ((((hc >> 3) ^ (n & 7))) << 3) + (hc & 7);
        Wt[dst] = __float2half(t[tx][ty + s * 8]);
    }
}

// ======================= fp16 mma GEMM: 256x128 CTA, 3-stage bulk pipeline ==
// Warps 4m x 2n, warp tile 64x64. A stage 32KB, B stage 16KB, 3 stages.
#define GNCHUNK  6
#define ASTG_B   32768
#define BSTG_B   16384
#define STG_B    (ASTG_B + BSTG_B)
#define GSM_TOT  (3 * STG_B + 24)

template<bool OUT_FLOAT>
__global__ __launch_bounds__(256, 1) void mma_gemm_h(
    const __half* __restrict__ A, const __half* __restrict__ Wt,
    const float* __restrict__ bias, void* __restrict__ Cout, int Ntot)
{
    extern __shared__ __half smh[];
    const uint32_t sbase = smem_u32(smh);
    uint32_t sAu[3], sBu[3], mb[3];
#pragma unroll
    for (int s = 0; s < 3; ++s) {
        sAu[s] = sbase + s * STG_B;
        sBu[s] = sbase + s * STG_B + ASTG_B;
        mb[s]  = sbase + 3 * STG_B + s * 8;
    }

    const int tid = threadIdx.x;
    const int wid = tid >> 5, lid = tid & 31;
    const int g = lid >> 2, t4 = lid & 3;
    const int grp4 = lid >> 3;
    const int x7 = lid & 7;
    const int wm = (wid >> 1) * 64;      // 4 m-warps
    const int wn = (wid & 1) * 64;       // 2 n-warps
    const int bm = blockIdx.y * 256;
    const int bn = blockIdx.x * 128;

    const uint32_t aRow = (uint32_t)(wm + (grp4 & 1) * 8 + x7) * 128;
    const int cA = grp4 >> 1;
    const uint32_t bRow = (uint32_t)(wn + (grp4 >> 1) * 8 + x7) * 128;
    const int cB = grp4 & 1;

    if (tid == 0) {
        MBARRIER_INIT(mb[0], 1); MBARRIER_INIT(mb[1], 1); MBARRIER_INIT(mb[2], 1);
    }
    __syncthreads();
    int ph[3] = {0, 0, 0};

    float acc[4][8][4];
#pragma unroll
    for (int i = 0; i < 4; ++i)
#pragma unroll
        for (int j = 0; j < 8; ++j)
#pragma unroll
            for (int q = 0; q < 4; ++q) acc[i][j][q] = 0.f;

    auto issue = [&](int c, int buf) {
        if (tid == 0) {
            MBARRIER_EXPECT_TX(mb[buf], (uint32_t)STG_B);
            CP_BULK(sAu[buf], A  + ((size_t)c * MROWS + bm) * 64, (uint32_t)ASTG_B, mb[buf]);
            CP_BULK(sBu[buf], Wt + ((size_t)c * Ntot  + bn) * 64, (uint32_t)BSTG_B, mb[buf]);
        }
    };

    issue(0, 0);
    issue(1, 1);
    for (int c = 0; c < GNCHUNK; ++c) {
        const int buf = c % 3;
        MBARRIER_WAIT_PARITY(mb[buf], ph[buf]);
        ph[buf] ^= 1;

#pragma unroll
        for (int ks = 0; ks < 4; ++ks) {
            uint32_t af[4][4], bf[8][2];
            const uint32_t aSw = (uint32_t)(((ks * 2 + cA) ^ x7) << 4);
            const uint32_t bSw = (uint32_t)(((ks * 2 + cB) ^ x7) << 4);
#pragma unroll
            for (int mi = 0; mi < 4; ++mi)
                ldsm_x4(af[mi][0], af[mi][1], af[mi][2], af[mi][3],
                        sAu[buf] + aRow + (uint32_t)(mi * 2048) + aSw);
#pragma unroll
            for (int p = 0; p < 4; ++p)
                ldsm_x4(bf[2*p][0], bf[2*p][1], bf[2*p+1][0], bf[2*p+1][1],
                        sBu[buf] + bRow + (uint32_t)(p * 2048) + bSw);
#pragma unroll
            for (int mi = 0; mi < 4; ++mi)
#pragma unroll
                for (int ni = 0; ni < 8; ++ni)
                    mma_f16(acc[mi][ni], af[mi], bf[ni]);
        }
        __syncthreads();               // buf free for reuse
        if (c + 2 < GNCHUNK) issue(c + 2, (c + 2) % 3);
    }

#pragma unroll
    for (int mi = 0; mi < 4; ++mi) {
#pragma unroll
        for (int ni = 0; ni < 8; ++ni) {
            const int row = bm + wm + mi * 16 + g;
            const int col = bn + wn + ni * 8 + t4 * 2;
            const float b0 = __ldg(&bias[col]), b1 = __ldg(&bias[col + 1]);
            float v00 = acc[mi][ni][0] + b0, v01 = acc[mi][ni][1] + b1;
            float v10 = acc[mi][ni][2] + b0, v11 = acc[mi][ni][3] + b1;
            if (OUT_FLOAT) {
                float* C = reinterpret_cast<float*>(Cout);
                *reinterpret_cast<float2*>(&C[(size_t)row * Ntot + col])       = make_float2(v00, v01);
                *reinterpret_cast<float2*>(&C[(size_t)(row + 8) * Ntot + col]) = make_float2(v10, v11);
            } else {
                __half* C = reinterpret_cast<__half*>(Cout);
                *reinterpret_cast<uint32_t*>(&C[(size_t)row * Ntot + col])       = pack_h2(v00, v01);
                *reinterpret_cast<uint32_t*>(&C[(size_t)(row + 8) * Ntot + col]) = pack_h2(v10, v11);
            }
        }
    }
}

// ======================= fp16 flash attention (unchanged) ===================
#define AT_THREADS 128
#define LDKH 40

__global__ __launch_bounds__(AT_THREADS, 1) void attn_f16_kernel(
    const __half* __restrict__ qkv, const __half* __restrict__ biasP,
    __half* __restrict__ out)
{
    __shared__ __half Ks[2][64 * LDKH];
    __shared__ __half Vs[2][64 * LDKH];
    const int h   = blockIdx.x;
    const int b   = blockIdx.y;
    const int tid = threadIdx.x;
    const int wid = tid >> 5, lid = tid & 31;
    const int g = lid >> 2, t4 = lid & 3;
    const int grp4 = lid >> 3;
    const int wm = blockIdx.z * 128 + wid * 32;
    const bool active = wm < NTOK;
    const __half* base = qkv + (size_t)b * NTOK * QKVC;
    const float scale = 0.17677669529663687f;
    const uint32_t KsU[2] = { smem_u32(Ks[0]), smem_u32(Ks[1]) };
    const uint32_t VsU[2] = { smem_u32(Vs[0]), smem_u32(Vs[1]) };

    const uint32_t kOff = (uint32_t)(((grp4 >> 1) * 8 + (lid & 7)) * LDKH
                                     + (grp4 & 1) * 8) * 2;
    const uint32_t vOff = (uint32_t)((lid & 15) * LDKH + (lid >> 4) * 8) * 2;

    uint32_t qa[2][2][4];
#pragma unroll
    for (int mi = 0; mi < 2; ++mi) {
        const int r0 = wm + mi * 16 + g, r1 = r0 + 8;
        const __half* q0 = base + (size_t)r0 * QKVC + h * HDIM;
        const __half* q1 = base + (size_t)r1 * QKVC + h * HDIM;
#pragma unroll
        for (int ks = 0; ks < 2; ++ks) {
            const int k2 = ks * 16 + 2 * t4;
            qa[mi][ks][0] = (r0 < NTOK) ? *reinterpret_cast<const uint32_t*>(q0 + k2) : 0u;
            qa[mi][ks][1] = (r1 < NTOK) ? *reinterpret_cast<const uint32_t*>(q1 + k2) : 0u;
            qa[mi][ks][2] = (r0 < NTOK) ? *reinterpret_cast<const uint32_t*>(q0 + k2 + 8) : 0u;
            qa[mi][ks][3] = (r1 < NTOK) ? *reinterpret_cast<const uint32_t*>(q1 + k2 + 8) : 0u;
        }
    }

    float o[2][4][4];
#pragma unroll
    for (int mi = 0; mi < 2; ++mi)
#pragma unroll
        for (int n = 0; n < 4; ++n)
#pragma unroll
            for (int q = 0; q < 4; ++q) o[mi][n][q] = 0.f;
    float mrow[2][2] = {{-1e30f, -1e30f}, {-1e30f, -1e30f}};
    float lrow[2][2] = {{0.f, 0.f}, {0.f, 0.f}};

    const __half* bp = biasP + ((size_t)h * NPAD + wm) * KPAD;

    auto load_kv = [&](int ch, int buf) {
        const int j0 = ch * 64;
#pragma unroll
        for (int i = 0; i < 2; ++i) {
            int f = tid + i * 128;
            int row = f >> 2, c16 = (f & 3) * 8;
            int kr = j0 + row;
            uint32_t pred = (kr < NTOK) ? 16u : 0u;
            const __half* rp = base + (size_t)kr * QKVC + h * HDIM + c16;
            CP_ASYNC16P(KsU[buf] + (uint32_t)(row * LDKH + c16) * 2, rp + CDIM, pred);
            CP_ASYNC16P(VsU[buf] + (uint32_t)(row * LDKH + c16) * 2, rp + 2 * CDIM, pred);
        }
    };

    auto compute = [&](auto NIc, auto NGRPc, int ch, int buf) {
        constexpr int NI   = decltype(NIc)::value;
        constexpr int NGRP = decltype(NGRPc)::value;
        const int j0 = ch * 64;
        if (!active) return;

        float c[2][8][4];
#pragma unroll
        for (int mi = 0; mi < 2; ++mi)
#pragma unroll
            for (int ni = 0; ni < NI; ++ni)
#pragma unroll
                for (int q = 0; q < 4; ++q) c[mi][ni][q] = 0.f;
#pragma unroll
        for (int ks = 0; ks < 2; ++ks) {
            uint32_t kb[8][2];
#pragma unroll
            for (int p = 0; p < (NI + 1) / 2; ++p)
                ldsm_x4(kb[2*p][0], kb[2*p][1], kb[2*p+1][0], kb[2*p+1][1],
                        KsU[buf] + kOff + (uint32_t)(p * 16 * LDKH * 2 + ks * 32));
#pragma unroll
            for (int mi = 0; mi < 2; ++mi)
#pragma unroll
                for (int ni = 0; ni < NI; ++ni)
                    mma_f16(c[mi][ni], qa[mi][ks], kb[ni]);
        }
#pragma unroll
        for (int mi = 0; mi < 2; ++mi) {
            const __half* b0p = bp + (size_t)(mi * 16 + g) * KPAD + j0 + 2 * t4;
            const __half* b1p = bp + (size_t)(mi * 16 + 8 + g) * KPAD + j0 + 2 * t4;
#pragma unroll
            for (int ni = 0; ni < NI; ++ni) {
                float2 bb0 = __half22float2(*reinterpret_cast<const __half2*>(b0p + ni * 8));
                float2 bb1 = __half22float2(*reinterpret_cast<const __half2*>(b1p + ni * 8));
                c[mi][ni][0] = c[mi][ni][0] * scale + bb0.x;
                c[mi][ni][1] = c[mi][ni][1] * scale + bb0.y;
                c[mi][ni][2] = c[mi][ni][2] * scale + bb1.x;
                c[mi][ni][3] = c[mi][ni][3] * scale + bb1.y;
            }
        }
#pragma unroll
        for (int mi = 0; mi < 2; ++mi) {
            float mx0 = c[mi][0][0], mx1 = c[mi][0][2];
#pragma unroll
            for (int ni = 0; ni < NI; ++ni) {
                mx0 = fmaxf(mx0, fmaxf(c[mi][ni][0], c[mi][ni][1]));
                mx1 = fmaxf(mx1, fmaxf(c[mi][ni][2], c[mi][ni][3]));
            }
            mx0 = fmaxf(mx0, __shfl_xor_sync(0xFFFFFFFF, mx0, 1));
            mx0 = fmaxf(mx0, __shfl_xor_sync(0xFFFFFFFF, mx0, 2));
            mx1 = fmaxf(mx1, __shfl_xor_sync(0xFFFFFFFF, mx1, 1));
            mx1 = fmaxf(mx1, __shfl_xor_sync(0xFFFFFFFF, mx1, 2));
            float nm0 = fmaxf(mrow[mi][0], mx0);
            float nm1 = fmaxf(mrow[mi][1], mx1);
            float cr0 = __expf(mrow[mi][0] - nm0);
            float cr1 = __expf(mrow[mi][1] - nm1);
            mrow[mi][0] = nm0; mrow[mi][1] = nm1;
#pragma unroll
            for (int n = 0; n < 4; ++n) {
                o[mi][n][0] *= cr0; o[mi][n][1] *= cr0;
                o[mi][n][2] *= cr1; o[mi][n][3] *= cr1;
            }
            float s0 = 0.f, s1 = 0.f;
#pragma unroll
            for (int ni = 0; ni < NI; ++ni) {
                c[mi][ni][0] = __expf(c[mi][ni][0] - nm0); s0 += c[mi][ni][0];
                c[mi][ni][1] = __expf(c[mi][ni][1] - nm0); s0 += c[mi][ni][1];
                c[mi][ni][2] = __expf(c[mi][ni][2] - nm1); s1 += c[mi][ni][2];
                c[mi][ni][3] = __expf(c[mi][ni][3] - nm1); s1 += c[mi][ni][3];
            }
            s0 += __shfl_xor_sync(0xFFFFFFFF, s0, 1);
            s0 += __shfl_xor_sync(0xFFFFFFFF, s0, 2);
            s1 += __shfl_xor_sync(0xFFFFFFFF, s1, 1);
            s1 += __shfl_xor_sync(0xFFFFFFFF, s1, 2);
            lrow[mi][0] = lrow[mi][0] * cr0 + s0;
            lrow[mi][1] = lrow[mi][1] * cr1 + s1;
#pragma unroll
            for (int ni = NI; ni < 2 * NGRP; ++ni)
#pragma unroll
                for (int q = 0; q < 4; ++q) c[mi][ni][q] = 0.f;
        }
#pragma unroll
        for (int grp = 0; grp < NGRP; ++grp) {
            uint32_t vb[4][2];
            const uint32_t va = VsU[buf] + vOff + (uint32_t)(grp * 16 * LDKH * 2);
            ldsm_x4_t(vb[0][0], vb[0][1], vb[1][0], vb[1][1], va);
            ldsm_x4_t(vb[2][0], vb[2][1], vb[3][0], vb[3][1], va + 32);
#pragma unroll
            for (int mi = 0; mi < 2; ++mi) {
                uint32_t pa[4];
                pa[0] = pack_h2(c[mi][2 * grp][0],     c[mi][2 * grp][1]);
                pa[1] = pack_h2(c[mi][2 * grp][2],     c[mi][2 * grp][3]);
                pa[2] = pack_h2(c[mi][2 * grp + 1][0], c[mi][2 * grp + 1][1]);
                pa[3] = pack_h2(c[mi][2 * grp + 1][2], c[mi][2 * grp + 1][3]);
#pragma unroll
                for (int n = 0; n < 4; ++n)
                    mma_f16(o[mi][n], pa, vb[n]);
            }
        }
    };

    load_kv(0, 0);
    CP_COMMIT();
    for (int ch = 0; ch < 5; ++ch) {
        const int bu = ch & 1;
        load_kv(ch + 1, bu ^ 1);
        CP_COMMIT();
        CP_WAIT1();
        __syncthreads();
        compute(IC<8>{}, IC<4>{}, ch, bu);
        __syncthreads();
    }
    CP_WAIT0();
    __syncthreads();
    compute(IC<3>{}, IC<2>{}, 5, 1);

    if (active) {
        const int chk = h >> 1;
        const int gbase = (h & 1) * 4;
#pragma unroll
        for (int mi = 0; mi < 2; ++mi) {
            const float i0 = 1.f / lrow[mi][0];
            const float i1 = 1.f / lrow[mi][1];
            const int r0 = wm + mi * 16 + g;
            const int r1 = r0 + 8;
            if (r0 < NTOK) {
                size_t rg = (size_t)b * NTOK + r0;
                __half* op = out + ((size_t)chk * MROWS + rg) * 64 + 2 * t4;
                const int rx = (int)(rg & 7);
#pragma unroll
                for (int n = 0; n < 4; ++n)
                    *reinterpret_cast<uint32_t*>(op + (((gbase + n) ^ rx) << 3)) =
                        pack_h2(o[mi][n][0] * i0, o[mi][n][1] * i0);
            }
            if (r1 < NTOK) {
                size_t rg = (size_t)b * NTOK + r1;
                __half* op = out + ((size_t)chk * MROWS + rg) * 64 + 2 * t4;
                const int rx = (int)(rg & 7);
#pragma unroll
                for (int n = 0; n < 4; ++n)
                    *reinterpret_cast<uint32_t*>(op + (((gbase + n) ^ rx) << 3)) =
                        pack_h2(o[mi][n][2] * i1, o[mi][n][3] * i1);
            }
        }
    }
}

// ---------------- launch ------------------------------------------------------
extern "C" void kernel_launch(void* const* d_in, const int* in_sizes, int n_in,
                              void* d_out, int out_size)
{
    const float* x       = (const float*)d_in[0];
    const float* qkv_w   = (const float*)d_in[1];
    const float* qkv_b   = (const float*)d_in[2];
    const float* proj_w  = (const float*)d_in[3];
    const float* proj_b  = (const float*)d_in[4];
    const float* bt      = (const float*)d_in[5];
    const int*   ridx    = (const int*)d_in[6];
    float*       out     = (float*)d_out;

    void *p_qkv, *p_att, *p_bias, *p_xh, *p_wqt, *p_wpt;
    cudaGetSymbolAddress(&p_qkv,  g_qkv);
    cudaGetSymbolAddress(&p_att,  g_att);
    cudaGetSymbolAddress(&p_bias, g_biasH);
    cudaGetSymbolAddress(&p_xh,   g_xh);
    cudaGetSymbolAddress(&p_wqt,  g_wqt);
    cudaGetSymbolAddress(&p_wpt,  g_wpt);
    __half* qkvh = (__half*)p_qkv;
    __half* atth = (__half*)p_att;
    __half* bias = (__half*)p_bias;
    __half* xh   = (__half*)p_xh;
    __half* wqt  = (__half*)p_wqt;
    __half* wpt  = (__half*)p_wpt;

    cudaFuncSetAttribute(mma_gemm_h<false>,
                         cudaFuncAttributeMaxDynamicSharedMemorySize, GSM_TOT);
    cudaFuncSetAttribute(mma_gemm_h<true>,
                         cudaFuncAttributeMaxDynamicSharedMemorySize, GSM_TOT);

    // 0) fused prep
    prep_kernel<<<PREP_BLOCKS, 256>>>(x, qkv_w, proj_w, bt, ridx,
                                      xh, wqt, wpt, bias);

    // 1) QKV projection (256x128 CTA, 3-stage bulk pipeline)
    mma_gemm_h<false><<<dim3(QKVC / 128, MROWS / 256), 256, GSM_TOT>>>(
        xh, wqt, qkv_b, qkvh, QKVC);

    // 2) fp16 flash attention
    attn_f16_kernel<<<dim3(NHEADS, NWIN, 3), AT_THREADS>>>(qkvh, bias, atth);

    // 3) output projection (256x128 CTA, 3-stage bulk pipeline)
    mma_gemm_h<true><<<dim3(CDIM / 128, MROWS / 256), 256, GSM_TOT>>>(
        atth, wpt, proj_b, out, CDIM);
}

// round 13
// speedup vs baseline: 1.0420x; 1.0420x over previous
#include <cuda_runtime.h>
#include <cuda_fp16.h>
#include <cstdint>
#include <cstdio>

#define NTOK   343
#define NWIN   256
#define NHEADS 12
#define HDIM   32
#define CDIM   384
#define MROWS  (NWIN * NTOK)     // 87808
#define QKVC   (3 * CDIM)        // 1152
#define NPAD   384
#define KPAD   384

// ---------------- scratch (static device globals) ---------------------------
__device__ __half g_qkv[(size_t)MROWS * QKVC];     // normal layout (attn input)
__device__ __half g_att[(size_t)MROWS * CDIM];     // chunk-major swizzled (proj A)
__device__ __half g_biasH[NHEADS * NPAD * KPAD];   // bias pre-scaled by log2e
__device__ __half g_xh[(size_t)MROWS * CDIM];      // chunk-major swizzled (qkv A)
__device__ __half g_wqt[(size_t)QKVC * CDIM];      // chunk-major swizzled (qkv B)
__device__ __half g_wpt[(size_t)CDIM * CDIM];      // chunk-major swizzled (proj B)

template<int N> struct IC { static constexpr int value = N; };

// ======================= helpers ============================================
__device__ __forceinline__ uint32_t smem_u32(const void* p) {
    uint32_t a;
    asm("{ .reg .u64 t; cvta.to.shared.u64 t, %1; cvt.u32.u64 %0, t; }" : "=r"(a) : "l"(p));
    return a;
}
__device__ __forceinline__ uint32_t pack_h2(float lo, float hi) {
    uint32_t r;
    asm("cvt.rn.f16x2.f32 %0, %1, %2;" : "=r"(r) : "f"(hi), "f"(lo));
    return r;
}
__device__ __forceinline__ float ex2f(float x) {
    float r;
    asm("ex2.approx.f32 %0, %1;" : "=f"(r) : "f"(x));
    return r;
}
__device__ __forceinline__ void ldsm_x4(uint32_t& r0, uint32_t& r1, uint32_t& r2,
                                        uint32_t& r3, uint32_t addr) {
    asm volatile("ldmatrix.sync.aligned.m8n8.x4.shared.b16 {%0,%1,%2,%3}, [%4];"
                 : "=r"(r0), "=r"(r1), "=r"(r2), "=r"(r3) : "r"(addr));
}
__device__ __forceinline__ void ldsm_x4_t(uint32_t& r0, uint32_t& r1, uint32_t& r2,
                                          uint32_t& r3, uint32_t addr) {
    asm volatile("ldmatrix.sync.aligned.m8n8.x4.trans.shared.b16 {%0,%1,%2,%3}, [%4];"
                 : "=r"(r0), "=r"(r1), "=r"(r2), "=r"(r3) : "r"(addr));
}
#define CP_ASYNC16P(dst, src, n) \
    asm volatile("cp.async.cg.shared.global [%0], [%1], 16, %2;" :: "r"(dst), "l"(src), "r"(n))
#define CP_COMMIT() asm volatile("cp.async.commit_group;" ::: "memory")
#define CP_WAIT1()  asm volatile("cp.async.wait_group 1;" ::: "memory")
#define CP_WAIT0()  asm volatile("cp.async.wait_group 0;" ::: "memory")

#define MBARRIER_INIT(mb, cnt) \
    asm volatile("mbarrier.init.shared.b64 [%0], %1;" :: "r"((uint32_t)(mb)), "r"((uint32_t)(cnt)) : "memory")
#define MBARRIER_EXPECT_TX(mb, bytes) \
    asm volatile("mbarrier.arrive.expect_tx.shared.b64 _, [%0], %1;" :: "r"((uint32_t)(mb)), "r"((uint32_t)(bytes)) : "memory")
#define CP_BULK(dst, src, bytes, mb) \
    asm volatile("cp.async.bulk.shared::cluster.global.mbarrier::complete_tx::bytes [%0], [%1], %2, [%3];" \
                 :: "r"((uint32_t)(dst)), "l"(src), "r"((uint32_t)(bytes)), "r"((uint32_t)(mb)) : "memory")
#define MBARRIER_WAIT_PARITY(mb, ph) do {                                         \
    uint32_t _mb = (uint32_t)(mb); uint32_t _p = (uint32_t)(ph); uint32_t _done;  \
    asm volatile("{\n\t.reg .pred p;\n\t"                                         \
        "mbarrier.try_wait.parity.acquire.cta.shared::cta.b64 p, [%1], %2;\n\t"   \
        "selp.b32 %0, 1, 0, p;\n\t}" : "=r"(_done) : "r"(_mb), "r"(_p) : "memory"); \
    if (!_done) {                                                                 \
        asm volatile("{\n\t.reg .pred P1;\n\t"                                    \
            "WL_%=:\n\t"                                                          \
            "mbarrier.try_wait.parity.acquire.cta.shared::cta.b64 P1, [%0], %1, 0x989680;\n\t" \
            "@P1 bra.uni WD_%=;\n\t"                                              \
            "bra.uni WL_%=;\n\t"                                                  \
            "WD_%=:\n\t}" :: "r"(_mb), "r"(_p) : "memory");                       \
    }                                                                             \
} while (0)

__device__ __forceinline__ void mma_f16(float* c, const uint32_t* a, const uint32_t* b) {
    asm volatile(
        "mma.sync.aligned.m16n8k16.row.col.f32.f16.f16.f32 "
        "{%0,%1,%2,%3}, {%4,%5,%6,%7}, {%8,%9}, {%0,%1,%2,%3};"
        : "+f"(c[0]), "+f"(c[1]), "+f"(c[2]), "+f"(c[3])
        : "r"(a[0]), "r"(a[1]), "r"(a[2]), "r"(a[3]), "r"(b[0]), "r"(b[1]));
}

// ======================= fused prep kernel ==================================
#define NBX  16464
#define NBB  6912
#define NBTQ 432
#define NBTP 144
#define PREP_BLOCKS (NBX + NBB + NBTQ + NBTP)
#define LOG2E 1.4426950408889634f

__global__ __launch_bounds__(256) void prep_kernel(
    const float* __restrict__ x, const float* __restrict__ qkv_w,
    const float* __restrict__ proj_w, const float* __restrict__ bt,
    const int* __restrict__ ridx,
    __half* __restrict__ xh, __half* __restrict__ wqt,
    __half* __restrict__ wpt, __half* __restrict__ bf)
{
    __shared__ float t[32][33];
    const int bid = blockIdx.x;
    const int tid = threadIdx.x;

    if (bid < NBX) {
        size_t e = ((size_t)bid * 256 + tid) * 8;
        int row = (int)(e / CDIM);
        int hcf = (int)(e % CDIM);
        int c   = hcf >> 6;
        int grp = (hcf & 63) >> 3;
        float4 v0 = *reinterpret_cast<const float4*>(x + e);
        float4 v1 = *reinterpret_cast<const float4*>(x + e + 4);
        uint4 o;
        o.x = pack_h2(v0.x, v0.y); o.y = pack_h2(v0.z, v0.w);
        o.z = pack_h2(v1.x, v1.y); o.w = pack_h2(v1.z, v1.w);
        size_t dst = ((size_t)c * MROWS + row) * 64 + ((grp ^ (row & 7)) << 3);
        *reinterpret_cast<uint4*>(xh + dst) = o;
        return;
    }
    if (bid < NBX + NBB) {
        int idx = (bid - NBX) * 256 + tid;
        int h   = idx / (NPAD * KPAD);
        int rem = idx - h * NPAD * KPAD;
        int r   = rem / KPAD;
        int k   = rem - r * KPAD;
        float v;
        if (k >= NTOK)      v = -60000.f;              // exp2(-60000+s) == 0
        else if (r >= NTOK) v = 0.f;
        else                v = bt[ridx[r * NTOK + k] * NHEADS + h] * LOG2E;
        bf[idx] = __float2half(v);
        return;
    }
    const int tx = tid & 31, ty = tid >> 5;
    const float* W; __half* Wt; int Nw, bx, by;
    if (bid < NBX + NBB + NBTQ) {
        int bb = bid - NBX - NBB;
        W = qkv_w; Wt = wqt; Nw = QKVC;
        bx = bb % (QKVC / 32); by = bb / (QKVC / 32);
    } else {
        int bb = bid - NBX - NBB - NBTQ;
        W = proj_w; Wt = wpt; Nw = CDIM;
        bx = bb % (CDIM / 32); by = bb / (CDIM / 32);
    }
    int n0 = bx * 32, k0 = by * 32;
#pragma unroll
    for (int s = 0; s < 4; ++s) {
        int k = k0 + ty + s * 8;
        t[ty + s * 8][tx] = W[(size_t)k * Nw + n0 + tx];
    }
    __syncthreads();
#pragma unroll
    for (int s = 0; s < 4; ++s) {
        int n = n0 + ty + s * 8;
        int k = k0 + tx;
        int c = k >> 6, hc = k & 63;
        size_t dst = ((size_t)c * Nw + n) * 64
                     + ((((hc >> 3) ^ (n & 7))) << 3) + (hc & 7);
        Wt[dst] = __float2half(t[tx][ty + s * 8]);
    }
}

// ======================= fp16 mma GEMM: 128x128 CTA, 3-stage bulk pipeline ==
// (R11 shape: warps 2m x 4n, warp tile 64x32, 2 CTA/SM; +1 pipeline stage)
#define GNCHUNK  6
#define ASTG_B   16384
#define STG_B    (2 * ASTG_B)             // A + B per stage = 32KB
#define GSM_TOT  (3 * STG_B + 24)         // 98328 B -> still 2 CTAs/SM

template<bool OUT_FLOAT>
__global__ __launch_bounds__(256, 2) void mma_gemm_h(
    const __half* __restrict__ A, const __half* __restrict__ Wt,
    const float* __restrict__ bias, void* __restrict__ Cout, int Ntot)
{
    extern __shared__ __half smh[];
    const uint32_t sbase = smem_u32(smh);
    uint32_t sAu[3], sBu[3], mb[3];
#pragma unroll
    for (int s = 0; s < 3; ++s) {
        sAu[s] = sbase + s * STG_B;
        sBu[s] = sbase + s * STG_B + ASTG_B;
        mb[s]  = sbase + 3 * STG_B + s * 8;
    }

    const int tid = threadIdx.x;
    const int wid = tid >> 5, lid = tid & 31;
    const int g = lid >> 2, t4 = lid & 3;
    const int grp4 = lid >> 3;
    const int x7 = lid & 7;
    const int wm = (wid & 1) * 64;
    const int wn = (wid >> 1) * 32;
    const int bm = blockIdx.y * 128;
    const int bn = blockIdx.x * 128;

    const uint32_t aRow = (uint32_t)(wm + (grp4 & 1) * 8 + x7) * 128;
    const int cA = grp4 >> 1;
    const uint32_t bRow = (uint32_t)(wn + (grp4 >> 1) * 8 + x7) * 128;
    const int cB = grp4 & 1;

    if (tid == 0) {
        MBARRIER_INIT(mb[0], 1); MBARRIER_INIT(mb[1], 1); MBARRIER_INIT(mb[2], 1);
    }
    __syncthreads();
    int ph[3] = {0, 0, 0};

    float acc[4][4][4];
#pragma unroll
    for (int i = 0; i < 4; ++i)
#pragma unroll
        for (int j = 0; j < 4; ++j)
#pragma unroll
            for (int q = 0; q < 4; ++q) acc[i][j][q] = 0.f;

    auto issue = [&](int c, int buf) {
        if (tid == 0) {
            MBARRIER_EXPECT_TX(mb[buf], (uint32_t)STG_B);
            CP_BULK(sAu[buf], A  + ((size_t)c * MROWS + bm) * 64, (uint32_t)ASTG_B, mb[buf]);
            CP_BULK(sBu[buf], Wt + ((size_t)c * Ntot  + bn) * 64, (uint32_t)ASTG_B, mb[buf]);
        }
    };

    issue(0, 0);
    issue(1, 1);
    for (int c = 0; c < GNCHUNK; ++c) {
        const int buf = c % 3;
        MBARRIER_WAIT_PARITY(mb[buf], ph[buf]);
        ph[buf] ^= 1;

#pragma unroll
        for (int ks = 0; ks < 4; ++ks) {
            uint32_t af[4][4], bf[4][2];
            const uint32_t aSw = (uint32_t)(((ks * 2 + cA) ^ x7) << 4);
            const uint32_t bSw = (uint32_t)(((ks * 2 + cB) ^ x7) << 4);
#pragma unroll
            for (int mi = 0; mi < 4; ++mi)
                ldsm_x4(af[mi][0], af[mi][1], af[mi][2], af[mi][3],
                        sAu[buf] + aRow + (uint32_t)(mi * 2048) + aSw);
            ldsm_x4(bf[0][0], bf[0][1], bf[1][0], bf[1][1], sBu[buf] + bRow + bSw);
            ldsm_x4(bf[2][0], bf[2][1], bf[3][0], bf[3][1], sBu[buf] + bRow + 2048 + bSw);
#pragma unroll
            for (int mi = 0; mi < 4; ++mi)
#pragma unroll
                for (int ni = 0; ni < 4; ++ni)
                    mma_f16(acc[mi][ni], af[mi], bf[ni]);
        }
        __syncthreads();               // buf consumed by all warps
        if (c + 2 < GNCHUNK) issue(c + 2, (c + 2) % 3);
    }

#pragma unroll
    for (int mi = 0; mi < 4; ++mi) {
#pragma unroll
        for (int ni = 0; ni < 4; ++ni) {
            const int row = bm + wm + mi * 16 + g;
            const int col = bn + wn + ni * 8 + t4 * 2;
            const float b0 = __ldg(&bias[col]), b1 = __ldg(&bias[col + 1]);
            float v00 = acc[mi][ni][0] + b0, v01 = acc[mi][ni][1] + b1;
            float v10 = acc[mi][ni][2] + b0, v11 = acc[mi][ni][3] + b1;
            if (OUT_FLOAT) {
                float* C = reinterpret_cast<float*>(Cout);
                *reinterpret_cast<float2*>(&C[(size_t)row * Ntot + col])       = make_float2(v00, v01);
                *reinterpret_cast<float2*>(&C[(size_t)(row + 8) * Ntot + col]) = make_float2(v10, v11);
            } else {
                __half* C = reinterpret_cast<__half*>(Cout);
                *reinterpret_cast<uint32_t*>(&C[(size_t)row * Ntot + col])       = pack_h2(v00, v01);
                *reinterpret_cast<uint32_t*>(&C[(size_t)(row + 8) * Ntot + col]) = pack_h2(v10, v11);
            }
        }
    }
}

// ======================= fp16 flash attention (exp2 softmax) ================
#define AT_THREADS 128
#define LDKH 40

__global__ __launch_bounds__(AT_THREADS, 1) void attn_f16_kernel(
    const __half* __restrict__ qkv, const __half* __restrict__ biasP,
    __half* __restrict__ out)
{
    __shared__ __half Ks[2][64 * LDKH];
    __shared__ __half Vs[2][64 * LDKH];
    const int h   = blockIdx.x;
    const int b   = blockIdx.y;
    const int tid = threadIdx.x;
    const int wid = tid >> 5, lid = tid & 31;
    const int g = lid >> 2, t4 = lid & 3;
    const int grp4 = lid >> 3;
    const int wm = blockIdx.z * 128 + wid * 32;
    const bool active = wm < NTOK;
    const __half* base = qkv + (size_t)b * NTOK * QKVC;
    const float scale = 0.17677669529663687f * LOG2E;   // folds log2e
    const uint32_t KsU[2] = { smem_u32(Ks[0]), smem_u32(Ks[1]) };
    const uint32_t VsU[2] = { smem_u32(Vs[0]), smem_u32(Vs[1]) };

    const uint32_t kOff = (uint32_t)(((grp4 >> 1) * 8 + (lid & 7)) * LDKH
                                     + (grp4 & 1) * 8) * 2;
    const uint32_t vOff = (uint32_t)((lid & 15) * LDKH + (lid >> 4) * 8) * 2;

    uint32_t qa[2][2][4];
#pragma unroll
    for (int mi = 0; mi < 2; ++mi) {
        const int r0 = wm + mi * 16 + g, r1 = r0 + 8;
        const __half* q0 = base + (size_t)r0 * QKVC + h * HDIM;
        const __half* q1 = base + (size_t)r1 * QKVC + h * HDIM;
#pragma unroll
        for (int ks = 0; ks < 2; ++ks) {
            const int k2 = ks * 16 + 2 * t4;
            qa[mi][ks][0] = (r0 < NTOK) ? *reinterpret_cast<const uint32_t*>(q0 + k2) : 0u;
            qa[mi][ks][1] = (r1 < NTOK) ? *reinterpret_cast<const uint32_t*>(q1 + k2) : 0u;
            qa[mi][ks][2] = (r0 < NTOK) ? *reinterpret_cast<const uint32_t*>(q0 + k2 + 8) : 0u;
            qa[mi][ks][3] = (r1 < NTOK) ? *reinterpret_cast<const uint32_t*>(q1 + k2 + 8) : 0u;
        }
    }

    float o[2][4][4];
#pragma unroll
    for (int mi = 0; mi < 2; ++mi)
#pragma unroll
        for (int n = 0; n < 4; ++n)
#pragma unroll
            for (int q = 0; q < 4; ++q) o[mi][n][q] = 0.f;
    float mrow[2][2] = {{-1e30f, -1e30f}, {-1e30f, -1e30f}};
    float lrow[2][2] = {{0.f, 0.f}, {0.f, 0.f}};

    const __half* bp = biasP + ((size_t)h * NPAD + wm) * KPAD;

    auto load_kv = [&](int ch, int buf) {
        const int j0 = ch * 64;
#pragma unroll
        for (int i = 0; i < 2; ++i) {
            int f = tid + i * 128;
            int row = f >> 2, c16 = (f & 3) * 8;
            int kr = j0 + row;
            uint32_t pred = (kr < NTOK) ? 16u : 0u;
            const __half* rp = base + (size_t)kr * QKVC + h * HDIM + c16;
            CP_ASYNC16P(KsU[buf] + (uint32_t)(row * LDKH + c16) * 2, rp + CDIM, pred);
            CP_ASYNC16P(VsU[buf] + (uint32_t)(row * LDKH + c16) * 2, rp + 2 * CDIM, pred);
        }
    };

    auto compute = [&](auto NIc, auto NGRPc, int ch, int buf) {
        constexpr int NI   = decltype(NIc)::value;
        constexpr int NGRP = decltype(NGRPc)::value;
        const int j0 = ch * 64;
        if (!active) return;

        float c[2][8][4];
#pragma unroll
        for (int mi = 0; mi < 2; ++mi)
#pragma unroll
            for (int ni = 0; ni < NI; ++ni)
#pragma unroll
                for (int q = 0; q < 4; ++q) c[mi][ni][q] = 0.f;
#pragma unroll
        for (int ks = 0; ks < 2; ++ks) {
            uint32_t kb[8][2];
#pragma unroll
            for (int p = 0; p < (NI + 1) / 2; ++p)
                ldsm_x4(kb[2*p][0], kb[2*p][1], kb[2*p+1][0], kb[2*p+1][1],
                        KsU[buf] + kOff + (uint32_t)(p * 16 * LDKH * 2 + ks * 32));
#pragma unroll
            for (int mi = 0; mi < 2; ++mi)
#pragma unroll
                for (int ni = 0; ni < NI; ++ni)
                    mma_f16(c[mi][ni], qa[mi][ks], kb[ni]);
        }
#pragma unroll
        for (int mi = 0; mi < 2; ++mi) {
            const __half* b0p = bp + (size_t)(mi * 16 + g) * KPAD + j0 + 2 * t4;
            const __half* b1p = bp + (size_t)(mi * 16 + 8 + g) * KPAD + j0 + 2 * t4;
#pragma unroll
            for (int ni = 0; ni < NI; ++ni) {
                float2 bb0 = __half22float2(*reinterpret_cast<const __half2*>(b0p + ni * 8));
                float2 bb1 = __half22float2(*reinterpret_cast<const __half2*>(b1p + ni * 8));
                c[mi][ni][0] = c[mi][ni][0] * scale + bb0.x;
                c[mi][ni][1] = c[mi][ni][1] * scale + bb0.y;
                c[mi][ni][2] = c[mi][ni][2] * scale + bb1.x;
                c[mi][ni][3] = c[mi][ni][3] * scale + bb1.y;
            }
        }
        // ---- online softmax in log2 domain --------------------------------
#pragma unroll
        for (int mi = 0; mi < 2; ++mi) {
            float mx0 = c[mi][0][0], mx1 = c[mi][0][2];
#pragma unroll
            for (int ni = 0; ni < NI; ++ni) {
                mx0 = fmaxf(mx0, fmaxf(c[mi][ni][0], c[mi][ni][1]));
                mx1 = fmaxf(mx1, fmaxf(c[mi][ni][2], c[mi][ni][3]));
            }
            mx0 = fmaxf(mx0, __shfl_xor_sync(0xFFFFFFFF, mx0, 1));
            mx0 = fmaxf(mx0, __shfl_xor_sync(0xFFFFFFFF, mx0, 2));
            mx1 = fmaxf(mx1, __shfl_xor_sync(0xFFFFFFFF, mx1, 1));
            mx1 = fmaxf(mx1, __shfl_xor_sync(0xFFFFFFFF, mx1, 2));
            float nm0 = fmaxf(mrow[mi][0], mx0);
            float nm1 = fmaxf(mrow[mi][1], mx1);
            float cr0 = ex2f(mrow[mi][0] - nm0);
            float cr1 = ex2f(mrow[mi][1] - nm1);
            mrow[mi][0] = nm0; mrow[mi][1] = nm1;
#pragma unroll
            for (int n = 0; n < 4; ++n) {
                o[mi][n][0] *= cr0; o[mi][n][1] *= cr0;
                o[mi][n][2] *= cr1; o[mi][n][3] *= cr1;
            }
            float s0 = 0.f, s1 = 0.f;
#pragma unroll
            for (int ni = 0; ni < NI; ++ni) {
                c[mi][ni][0] = ex2f(c[mi][ni][0] - nm0); s0 += c[mi][ni][0];
                c[mi][ni][1] = ex2f(c[mi][ni][1] - nm0); s0 += c[mi][ni][1];
                c[mi][ni][2] = ex2f(c[mi][ni][2] - nm1); s1 += c[mi][ni][2];
                c[mi][ni][3] = ex2f(c[mi][ni][3] - nm1); s1 += c[mi][ni][3];
            }
            s0 += __shfl_xor_sync(0xFFFFFFFF, s0, 1);
            s0 += __shfl_xor_sync(0xFFFFFFFF, s0, 2);
            s1 += __shfl_xor_sync(0xFFFFFFFF, s1, 1);
            s1 += __shfl_xor_sync(0xFFFFFFFF, s1, 2);
            lrow[mi][0] = lrow[mi][0] * cr0 + s0;
            lrow[mi][1] = lrow[mi][1] * cr1 + s1;
#pragma unroll
            for (int ni = NI; ni < 2 * NGRP; ++ni)
#pragma unroll
                for (int q = 0; q < 4; ++q) c[mi][ni][q] = 0.f;
        }
#pragma unroll
        for (int grp = 0; grp < NGRP; ++grp) {
            uint32_t vb[4][2];
            const uint32_t va = VsU[buf] + vOff + (uint32_t)(grp * 16 * LDKH * 2);
            ldsm_x4_t(vb[0][0], vb[0][1], vb[1][0], vb[1][1], va);
            ldsm_x4_t(vb[2][0], vb[2][1], vb[3][0], vb[3][1], va + 32);
#pragma unroll
            for (int mi = 0; mi < 2; ++mi) {
                uint32_t pa[4];
                pa[0] = pack_h2(c[mi][2 * grp][0],     c[mi][2 * grp][1]);
                pa[1] = pack_h2(c[mi][2 * grp][2],     c[mi][2 * grp][3]);
                pa[2] = pack_h2(c[mi][2 * grp + 1][0], c[mi][2 * grp + 1][1]);
                pa[3] = pack_h2(c[mi][2 * grp + 1][2], c[mi][2 * grp + 1][3]);
#pragma unroll
                for (int n = 0; n < 4; ++n)
                    mma_f16(o[mi][n], pa, vb[n]);
            }
        }
    };

    load_kv(0, 0);
    CP_COMMIT();
    for (int ch = 0; ch < 5; ++ch) {
        const int bu = ch & 1;
        load_kv(ch + 1, bu ^ 1);
        CP_COMMIT();
        CP_WAIT1();
        __syncthreads();
        compute(IC<8>{}, IC<4>{}, ch, bu);
        __syncthreads();
    }
    CP_WAIT0();
    __syncthreads();
    compute(IC<3>{}, IC<2>{}, 5, 1);

    if (active) {
        const int chk = h >> 1;
        const int gbase = (h & 1) * 4;
#pragma unroll
        for (int mi = 0; mi < 2; ++mi) {
            const float i0 = 1.f / lrow[mi][0];
            const float i1 = 1.f / lrow[mi][1];
            const int r0 = wm + mi * 16 + g;
            const int r1 = r0 + 8;
            if (r0 < NTOK) {
                size_t rg = (size_t)b * NTOK + r0;
                __half* op = out + ((size_t)chk * MROWS + rg) * 64 + 2 * t4;
                const int rx = (int)(rg & 7);
#pragma unroll
                for (int n = 0; n < 4; ++n)
                    *reinterpret_cast<uint32_t*>(op + (((gbase + n) ^ rx) << 3)) =
                        pack_h2(o[mi][n][0] * i0, o[mi][n][1] * i0);
            }
            if (r1 < NTOK) {
                size_t rg = (size_t)b * NTOK + r1;
                __half* op = out + ((size_t)chk * MROWS + rg) * 64 + 2 * t4;
                const int rx = (int)(rg & 7);
#pragma unroll
                for (int n = 0; n < 4; ++n)
                    *reinterpret_cast<uint32_t*>(op + (((gbase + n) ^ rx) << 3)) =
                        pack_h2(o[mi][n][2] * i1, o[mi][n][3] * i1);
            }
        }
    }
}

// ---------------- launch ------------------------------------------------------
extern "C" void kernel_launch(void* const* d_in, const int* in_sizes, int n_in,
                              void* d_out, int out_size)
{
    const float* x       = (const float*)d_in[0];
    const float* qkv_w   = (const float*)d_in[1];
    const float* qkv_b   = (const float*)d_in[2];
    const float* proj_w  = (const float*)d_in[3];
    const float* proj_b  = (const float*)d_in[4];
    const float* bt      = (const float*)d_in[5];
    const int*   ridx    = (const int*)d_in[6];
    float*       out     = (float*)d_out;

    void *p_qkv, *p_att, *p_bias, *p_xh, *p_wqt, *p_wpt;
    cudaGetSymbolAddress(&p_qkv,  g_qkv);
    cudaGetSymbolAddress(&p_att,  g_att);
    cudaGetSymbolAddress(&p_bias, g_biasH);
    cudaGetSymbolAddress(&p_xh,   g_xh);
    cudaGetSymbolAddress(&p_wqt,  g_wqt);
    cudaGetSymbolAddress(&p_wpt,  g_wpt);
    __half* qkvh = (__half*)p_qkv;
    __half* atth = (__half*)p_att;
    __half* bias = (__half*)p_bias;
    __half* xh   = (__half*)p_xh;
    __half* wqt  = (__half*)p_wqt;
    __half* wpt  = (__half*)p_wpt;

    cudaFuncSetAttribute(mma_gemm_h<false>,
                         cudaFuncAttributeMaxDynamicSharedMemorySize, GSM_TOT);
    cudaFuncSetAttribute(mma_gemm_h<true>,
                         cudaFuncAttributeMaxDynamicSharedMemorySize, GSM_TOT);

    // 0) fused prep
    prep_kernel<<<PREP_BLOCKS, 256>>>(x, qkv_w, proj_w, bt, ridx,
                                      xh, wqt, wpt, bias);

    // 1) QKV projection (128x128 CTA, 3-stage bulk pipeline, 2 CTA/SM)
    mma_gemm_h<false><<<dim3(QKVC / 128, MROWS / 128), 256, GSM_TOT>>>(
        xh, wqt, qkv_b, qkvh, QKVC);

    // 2) fp16 flash attention (exp2 softmax)
    attn_f16_kernel<<<dim3(NHEADS, NWIN, 3), AT_THREADS>>>(qkvh, bias, atth);

    // 3) output projection (128x128 CTA, 3-stage bulk pipeline, 2 CTA/SM)
    mma_gemm_h<true><<<dim3(CDIM / 128, MROWS / 128), 256, GSM_TOT>>>(
        atth, wpt, proj_b, out, CDIM);
}

// round 14
// speedup vs baseline: 1.0635x; 1.0206x over previous
#include <cuda_runtime.h>
#include <cuda_fp16.h>
#include <cstdint>
#include <cstdio>

#define NTOK   343
#define NWIN   256
#define NHEADS 12
#define HDIM   32
#define CDIM   384
#define MROWS  (NWIN * NTOK)     // 87808
#define QKVC   (3 * CDIM)        // 1152
#define NPAD   384
#define KPAD   384

// ---------------- scratch (static device globals) ---------------------------
__device__ __half g_qkv[(size_t)MROWS * QKVC];     // normal layout (attn input)
__device__ __half g_att[(size_t)MROWS * CDIM];     // chunk-major swizzled (proj A)
__device__ __half g_biasH[NHEADS * NPAD * KPAD];   // bias pre-scaled by log2e
__device__ __half g_xh[(size_t)MROWS * CDIM];      // chunk-major swizzled (qkv A)
__device__ __half g_wqt[(size_t)QKVC * CDIM];      // chunk-major swizzled (qkv B)
__device__ __half g_wpt[(size_t)CDIM * CDIM];      // chunk-major swizzled (proj B)

template<int N> struct IC { static constexpr int value = N; };

// ======================= helpers ============================================
__device__ __forceinline__ uint32_t smem_u32(const void* p) {
    uint32_t a;
    asm("{ .reg .u64 t; cvta.to.shared.u64 t, %1; cvt.u32.u64 %0, t; }" : "=r"(a) : "l"(p));
    return a;
}
__device__ __forceinline__ uint32_t pack_h2(float lo, float hi) {
    uint32_t r;
    asm("cvt.rn.f16x2.f32 %0, %1, %2;" : "=r"(r) : "f"(hi), "f"(lo));
    return r;
}
__device__ __forceinline__ float ex2f(float x) {
    float r;
    asm("ex2.approx.f32 %0, %1;" : "=f"(r) : "f"(x));
    return r;
}
__device__ __forceinline__ uint32_t ex2_h2(uint32_t x) {
    uint32_t r;
    asm("ex2.approx.f16x2 %0, %1;" : "=r"(r) : "r"(x));
    return r;
}
__device__ __forceinline__ uint32_t hmul2(uint32_t a, uint32_t b) {
    uint32_t r;
    asm("mul.f16x2 %0, %1, %2;" : "=r"(r) : "r"(a), "r"(b));
    return r;
}
__device__ __forceinline__ void ldsm_x4(uint32_t& r0, uint32_t& r1, uint32_t& r2,
                                        uint32_t& r3, uint32_t addr) {
    asm volatile("ldmatrix.sync.aligned.m8n8.x4.shared.b16 {%0,%1,%2,%3}, [%4];"
                 : "=r"(r0), "=r"(r1), "=r"(r2), "=r"(r3) : "r"(addr));
}
__device__ __forceinline__ void ldsm_x4_t(uint32_t& r0, uint32_t& r1, uint32_t& r2,
                                          uint32_t& r3, uint32_t addr) {
    asm volatile("ldmatrix.sync.aligned.m8n8.x4.trans.shared.b16 {%0,%1,%2,%3}, [%4];"
                 : "=r"(r0), "=r"(r1), "=r"(r2), "=r"(r3) : "r"(addr));
}
__device__ __forceinline__ void ldsm_x2_t(uint32_t& r0, uint32_t& r1, uint32_t addr) {
    asm volatile("ldmatrix.sync.aligned.m8n8.x2.trans.shared.b16 {%0,%1}, [%2];"
                 : "=r"(r0), "=r"(r1) : "r"(addr));
}
#define CP_ASYNC16P(dst, src, n) \
    asm volatile("cp.async.cg.shared.global [%0], [%1], 16, %2;" :: "r"(dst), "l"(src), "r"(n))
#define CP_COMMIT() asm volatile("cp.async.commit_group;" ::: "memory")
#define CP_WAIT1()  asm volatile("cp.async.wait_group 1;" ::: "memory")
#define CP_WAIT0()  asm volatile("cp.async.wait_group 0;" ::: "memory")

#define MBARRIER_INIT(mb, cnt) \
    asm volatile("mbarrier.init.shared.b64 [%0], %1;" :: "r"((uint32_t)(mb)), "r"((uint32_t)(cnt)) : "memory")
#define MBARRIER_EXPECT_TX(mb, bytes) \
    asm volatile("mbarrier.arrive.expect_tx.shared.b64 _, [%0], %1;" :: "r"((uint32_t)(mb)), "r"((uint32_t)(bytes)) : "memory")
#define CP_BULK(dst, src, bytes, mb) \
    asm volatile("cp.async.bulk.shared::cluster.global.mbarrier::complete_tx::bytes [%0], [%1], %2, [%3];" \
                 :: "r"((uint32_t)(dst)), "l"(src), "r"((uint32_t)(bytes)), "r"((uint32_t)(mb)) : "memory")
#define MBARRIER_WAIT_PARITY(mb, ph) do {                                         \
    uint32_t _mb = (uint32_t)(mb); uint32_t _p = (uint32_t)(ph); uint32_t _done;  \
    asm volatile("{\n\t.reg .pred p;\n\t"                                         \
        "mbarrier.try_wait.parity.acquire.cta.shared::cta.b64 p, [%1], %2;\n\t"   \
        "selp.b32 %0, 1, 0, p;\n\t}" : "=r"(_done) : "r"(_mb), "r"(_p) : "memory"); \
    if (!_done) {                                                                 \
        asm volatile("{\n\t.reg .pred P1;\n\t"                                    \
            "WL_%=:\n\t"                                                          \
            "mbarrier.try_wait.parity.acquire.cta.shared::cta.b64 P1, [%0], %1, 0x989680;\n\t" \
            "@P1 bra.uni WD_%=;\n\t"                                              \
            "bra.uni WL_%=;\n\t"                                                  \
            "WD_%=:\n\t}" :: "r"(_mb), "r"(_p) : "memory");                       \
    }                                                                             \
} while (0)

__device__ __forceinline__ void mma_f16(float* c, const uint32_t* a, const uint32_t* b) {
    asm volatile(
        "mma.sync.aligned.m16n8k16.row.col.f32.f16.f16.f32 "
        "{%0,%1,%2,%3}, {%4,%5,%6,%7}, {%8,%9}, {%0,%1,%2,%3};"
        : "+f"(c[0]), "+f"(c[1]), "+f"(c[2]), "+f"(c[3])
        : "r"(a[0]), "r"(a[1]), "r"(a[2]), "r"(a[3]), "r"(b[0]), "r"(b[1]));
}

// ======================= fused prep kernel ==================================
#define NBX  16464
#define NBB  6912
#define NBTQ 432
#define NBTP 144
#define PREP_BLOCKS (NBX + NBB + NBTQ + NBTP)
#define LOG2E 1.4426950408889634f

__global__ __launch_bounds__(256) void prep_kernel(
    const float* __restrict__ x, const float* __restrict__ qkv_w,
    const float* __restrict__ proj_w, const float* __restrict__ bt,
    const int* __restrict__ ridx,
    __half* __restrict__ xh, __half* __restrict__ wqt,
    __half* __restrict__ wpt, __half* __restrict__ bf)
{
    __shared__ float t[32][33];
    const int bid = blockIdx.x;
    const int tid = threadIdx.x;

    if (bid < NBX) {
        size_t e = ((size_t)bid * 256 + tid) * 8;
        int row = (int)(e / CDIM);
        int hcf = (int)(e % CDIM);
        int c   = hcf >> 6;
        int grp = (hcf & 63) >> 3;
        float4 v0 = *reinterpret_cast<const float4*>(x + e);
        float4 v1 = *reinterpret_cast<const float4*>(x + e + 4);
        uint4 o;
        o.x = pack_h2(v0.x, v0.y); o.y = pack_h2(v0.z, v0.w);
        o.z = pack_h2(v1.x, v1.y); o.w = pack_h2(v1.z, v1.w);
        size_t dst = ((size_t)c * MROWS + row) * 64 + ((grp ^ (row & 7)) << 3);
        *reinterpret_cast<uint4*>(xh + dst) = o;
        return;
    }
    if (bid < NBX + NBB) {
        int idx = (bid - NBX) * 256 + tid;
        int h   = idx / (NPAD * KPAD);
        int rem = idx - h * NPAD * KPAD;
        int r   = rem / KPAD;
        int k   = rem - r * KPAD;
        float v;
        if (k >= NTOK)      v = -60000.f;
        else if (r >= NTOK) v = 0.f;
        else                v = bt[ridx[r * NTOK + k] * NHEADS + h] * LOG2E;
        bf[idx] = __float2half(v);
        return;
    }
    const int tx = tid & 31, ty = tid >> 5;
    const float* W; __half* Wt; int Nw, bx, by;
    if (bid < NBX + NBB + NBTQ) {
        int bb = bid - NBX - NBB;
        W = qkv_w; Wt = wqt; Nw = QKVC;
        bx = bb % (QKVC / 32); by = bb / (QKVC / 32);
    } else {
        int bb = bid - NBX - NBB - NBTQ;
        W = proj_w; Wt = wpt; Nw = CDIM;
        bx = bb % (CDIM / 32); by = bb / (CDIM / 32);
    }
    int n0 = bx * 32, k0 = by * 32;
#pragma unroll
    for (int s = 0; s < 4; ++s) {
        int k = k0 + ty + s * 8;
        t[ty + s * 8][tx] = W[(size_t)k * Nw + n0 + tx];
    }
    __syncthreads();
#pragma unroll
    for (int s = 0; s < 4; ++s) {
        int n = n0 + ty + s * 8;
        int k = k0 + tx;
        int c = k >> 6, hc = k & 63;
        size_t dst = ((size_t)c * Nw + n) * 64
                     + ((((hc >> 3) ^ (n & 7))) << 3) + (hc & 7);
        Wt[dst] = __float2half(t[tx][ty + s * 8]);
    }
}

// ======================= fp16 mma GEMM (R13, unchanged) =====================
#define GNCHUNK  6
#define ASTG_B   16384
#define STG_B    (2 * ASTG_B)
#define GSM_TOT  (3 * STG_B + 24)

template<bool OUT_FLOAT>
__global__ __launch_bounds__(256, 2) void mma_gemm_h(
    const __half* __restrict__ A, const __half* __restrict__ Wt,
    const float* __restrict__ bias, void* __restrict__ Cout, int Ntot)
{
    extern __shared__ __half smh[];
    const uint32_t sbase = smem_u32(smh);
    uint32_t sAu[3], sBu[3], mb[3];
#pragma unroll
    for (int s = 0; s < 3; ++s) {
        sAu[s] = sbase + s * STG_B;
        sBu[s] = sbase + s * STG_B + ASTG_B;
        mb[s]  = sbase + 3 * STG_B + s * 8;
    }

    const int tid = threadIdx.x;
    const int wid = tid >> 5, lid = tid & 31;
    const int g = lid >> 2, t4 = lid & 3;
    const int grp4 = lid >> 3;
    const int x7 = lid & 7;
    const int wm = (wid & 1) * 64;
    const int wn = (wid >> 1) * 32;
    const int bm = blockIdx.y * 128;
    const int bn = blockIdx.x * 128;

    const uint32_t aRow = (uint32_t)(wm + (grp4 & 1) * 8 + x7) * 128;
    const int cA = grp4 >> 1;
    const uint32_t bRow = (uint32_t)(wn + (grp4 >> 1) * 8 + x7) * 128;
    const int cB = grp4 & 1;

    if (tid == 0) {
        MBARRIER_INIT(mb[0], 1); MBARRIER_INIT(mb[1], 1); MBARRIER_INIT(mb[2], 1);
    }
    __syncthreads();
    int ph[3] = {0, 0, 0};

    float acc[4][4][4];
#pragma unroll
    for (int i = 0; i < 4; ++i)
#pragma unroll
        for (int j = 0; j < 4; ++j)
#pragma unroll
            for (int q = 0; q < 4; ++q) acc[i][j][q] = 0.f;

    auto issue = [&](int c, int buf) {
        if (tid == 0) {
            MBARRIER_EXPECT_TX(mb[buf], (uint32_t)STG_B);
            CP_BULK(sAu[buf], A  + ((size_t)c * MROWS + bm) * 64, (uint32_t)ASTG_B, mb[buf]);
            CP_BULK(sBu[buf], Wt + ((size_t)c * Ntot  + bn) * 64, (uint32_t)ASTG_B, mb[buf]);
        }
    };

    issue(0, 0);
    issue(1, 1);
    for (int c = 0; c < GNCHUNK; ++c) {
        const int buf = c % 3;
        MBARRIER_WAIT_PARITY(mb[buf], ph[buf]);
        ph[buf] ^= 1;

#pragma unroll
        for (int ks = 0; ks < 4; ++ks) {
            uint32_t af[4][4], bf[4][2];
            const uint32_t aSw = (uint32_t)(((ks * 2 + cA) ^ x7) << 4);
            const uint32_t bSw = (uint32_t)(((ks * 2 + cB) ^ x7) << 4);
#pragma unroll
            for (int mi = 0; mi < 4; ++mi)
                ldsm_x4(af[mi][0], af[mi][1], af[mi][2], af[mi][3],
                        sAu[buf] + aRow + (uint32_t)(mi * 2048) + aSw);
            ldsm_x4(bf[0][0], bf[0][1], bf[1][0], bf[1][1], sBu[buf] + bRow + bSw);
            ldsm_x4(bf[2][0], bf[2][1], bf[3][0], bf[3][1], sBu[buf] + bRow + 2048 + bSw);
#pragma unroll
            for (int mi = 0; mi < 4; ++mi)
#pragma unroll
                for (int ni = 0; ni < 4; ++ni)
                    mma_f16(acc[mi][ni], af[mi], bf[ni]);
        }
        __syncthreads();
        if (c + 2 < GNCHUNK) issue(c + 2, (c + 2) % 3);
    }

#pragma unroll
    for (int mi = 0; mi < 4; ++mi) {
#pragma unroll
        for (int ni = 0; ni < 4; ++ni) {
            const int row = bm + wm + mi * 16 + g;
            const int col = bn + wn + ni * 8 + t4 * 2;
            const float b0 = __ldg(&bias[col]), b1 = __ldg(&bias[col + 1]);
            float v00 = acc[mi][ni][0] + b0, v01 = acc[mi][ni][1] + b1;
            float v10 = acc[mi][ni][2] + b0, v11 = acc[mi][ni][3] + b1;
            if (OUT_FLOAT) {
                float* C = reinterpret_cast<float*>(Cout);
                *reinterpret_cast<float2*>(&C[(size_t)row * Ntot + col])       = make_float2(v00, v01);
                *reinterpret_cast<float2*>(&C[(size_t)(row + 8) * Ntot + col]) = make_float2(v10, v11);
            } else {
                __half* C = reinterpret_cast<__half*>(Cout);
                *reinterpret_cast<uint32_t*>(&C[(size_t)row * Ntot + col])       = pack_h2(v00, v01);
                *reinterpret_cast<uint32_t*>(&C[(size_t)(row + 8) * Ntot + col]) = pack_h2(v10, v11);
            }
        }
    }
}

// ======================= fp16 flash attention v2 ============================
// - scale folded into Q frags (fp16, once)
// - S accumulators initialized from bias (no scale+bias pass)
// - P = ex2.f16x2 directly into PV A-fragments
// - row-sum l via ones-column in V pad space (col 32), fp32 mma accumulation
#define AT_THREADS 128
#define LDKH 40

__global__ __launch_bounds__(AT_THREADS, 1) void attn_f16_kernel(
    const __half* __restrict__ qkv, const __half* __restrict__ biasP,
    __half* __restrict__ out)
{
    __shared__ __half Ks[2][64 * LDKH];
    __shared__ __half Vs[2][64 * LDKH];
    const int h   = blockIdx.x;
    const int b   = blockIdx.y;
    const int tid = threadIdx.x;
    const int wid = tid >> 5, lid = tid & 31;
    const int g = lid >> 2, t4 = lid & 3;
    const int grp4 = lid >> 3;
    const int wm = blockIdx.z * 128 + wid * 32;
    const bool active = wm < NTOK;
    const __half* base = qkv + (size_t)b * NTOK * QKVC;
    const float scale = 0.17677669529663687f * LOG2E;
    const uint32_t KsU[2] = { smem_u32(Ks[0]), smem_u32(Ks[1]) };
    const uint32_t VsU[2] = { smem_u32(Vs[0]), smem_u32(Vs[1]) };

    const uint32_t kOff = (uint32_t)(((grp4 >> 1) * 8 + (lid & 7)) * LDKH
                                     + (grp4 & 1) * 8) * 2;
    const uint32_t vOff = (uint32_t)((lid & 15) * LDKH + (lid >> 4) * 8) * 2;

    // ones-column init in V pad space (col 32 = 1.0, cols 33..39 = 0), both bufs
    {
        int buf = tid >> 6, row = tid & 63;
        uint4 ones = make_uint4(0x00003C00u, 0u, 0u, 0u);
        *reinterpret_cast<uint4*>(&Vs[buf][row * LDKH + 32]) = ones;
    }

    // ---- Q a-frags from global, scale folded in fp16 ----------------------
    uint32_t qa[2][2][4];
    {
        const uint32_t sc2 = pack_h2(scale, scale);
#pragma unroll
        for (int mi = 0; mi < 2; ++mi) {
            const int r0 = wm + mi * 16 + g, r1 = r0 + 8;
            const __half* q0 = base + (size_t)r0 * QKVC + h * HDIM;
            const __half* q1 = base + (size_t)r1 * QKVC + h * HDIM;
#pragma unroll
            for (int ks = 0; ks < 2; ++ks) {
                const int k2 = ks * 16 + 2 * t4;
                qa[mi][ks][0] = (r0 < NTOK) ? hmul2(*reinterpret_cast<const uint32_t*>(q0 + k2), sc2) : 0u;
                qa[mi][ks][1] = (r1 < NTOK) ? hmul2(*reinterpret_cast<const uint32_t*>(q1 + k2), sc2) : 0u;
                qa[mi][ks][2] = (r0 < NTOK) ? hmul2(*reinterpret_cast<const uint32_t*>(q0 + k2 + 8), sc2) : 0u;
                qa[mi][ks][3] = (r1 < NTOK) ? hmul2(*reinterpret_cast<const uint32_t*>(q1 + k2 + 8), sc2) : 0u;
            }
        }
    }

    float o[2][4][4];
    float osum[2][4];
#pragma unroll
    for (int mi = 0; mi < 2; ++mi) {
#pragma unroll
        for (int n = 0; n < 4; ++n)
#pragma unroll
            for (int q = 0; q < 4; ++q) o[mi][n][q] = 0.f;
#pragma unroll
        for (int q = 0; q < 4; ++q) osum[mi][q] = 0.f;
    }
    float mrow[2][2] = {{-1e30f, -1e30f}, {-1e30f, -1e30f}};

    const __half* bp = biasP + ((size_t)h * NPAD + wm) * KPAD;

    auto load_kv = [&](int ch, int buf) {
        const int j0 = ch * 64;
#pragma unroll
        for (int i = 0; i < 2; ++i) {
            int f = tid + i * 128;
            int row = f >> 2, c16 = (f & 3) * 8;
            int kr = j0 + row;
            uint32_t pred = (kr < NTOK) ? 16u : 0u;
            const __half* rp = base + (size_t)kr * QKVC + h * HDIM + c16;
            CP_ASYNC16P(KsU[buf] + (uint32_t)(row * LDKH + c16) * 2, rp + CDIM, pred);
            CP_ASYNC16P(VsU[buf] + (uint32_t)(row * LDKH + c16) * 2, rp + 2 * CDIM, pred);
        }
    };

    auto compute = [&](auto NIc, auto NGRPc, int ch, int buf) {
        constexpr int NI   = decltype(NIc)::value;
        constexpr int NGRP = decltype(NGRPc)::value;
        const int j0 = ch * 64;
        if (!active) return;

        // ---- S accumulators initialized from bias -------------------------
        float c[2][8][4];
#pragma unroll
        for (int mi = 0; mi < 2; ++mi) {
            const __half* b0p = bp + (size_t)(mi * 16 + g) * KPAD + j0 + 2 * t4;
            const __half* b1p = bp + (size_t)(mi * 16 + 8 + g) * KPAD + j0 + 2 * t4;
#pragma unroll
            for (int ni = 0; ni < NI; ++ni) {
                float2 bb0 = __half22float2(*reinterpret_cast<const __half2*>(b0p + ni * 8));
                float2 bb1 = __half22float2(*reinterpret_cast<const __half2*>(b1p + ni * 8));
                c[mi][ni][0] = bb0.x; c[mi][ni][1] = bb0.y;
                c[mi][ni][2] = bb1.x; c[mi][ni][3] = bb1.y;
            }
        }
        // ---- S += (scale*Q) K^T -------------------------------------------
#pragma unroll
        for (int ks = 0; ks < 2; ++ks) {
            uint32_t kb[8][2];
#pragma unroll
            for (int p = 0; p < (NI + 1) / 2; ++p)
                ldsm_x4(kb[2*p][0], kb[2*p][1], kb[2*p+1][0], kb[2*p+1][1],
                        KsU[buf] + kOff + (uint32_t)(p * 16 * LDKH * 2 + ks * 32));
#pragma unroll
            for (int mi = 0; mi < 2; ++mi)
#pragma unroll
                for (int ni = 0; ni < NI; ++ni)
                    mma_f16(c[mi][ni], qa[mi][ks], kb[ni]);
        }
        // ---- online softmax: P directly in f16x2 --------------------------
        uint32_t pu[2][2 * NGRP][2];
#pragma unroll
        for (int mi = 0; mi < 2; ++mi) {
            float mx0 = c[mi][0][0], mx1 = c[mi][0][2];
#pragma unroll
            for (int ni = 0; ni < NI; ++ni) {
                mx0 = fmaxf(mx0, fmaxf(c[mi][ni][0], c[mi][ni][1]));
                mx1 = fmaxf(mx1, fmaxf(c[mi][ni][2], c[mi][ni][3]));
            }
            mx0 = fmaxf(mx0, __shfl_xor_sync(0xFFFFFFFF, mx0, 1));
            mx0 = fmaxf(mx0, __shfl_xor_sync(0xFFFFFFFF, mx0, 2));
            mx1 = fmaxf(mx1, __shfl_xor_sync(0xFFFFFFFF, mx1, 1));
            mx1 = fmaxf(mx1, __shfl_xor_sync(0xFFFFFFFF, mx1, 2));
            float nm0 = fmaxf(mrow[mi][0], mx0);
            float nm1 = fmaxf(mrow[mi][1], mx1);
            float cr0 = ex2f(mrow[mi][0] - nm0);
            float cr1 = ex2f(mrow[mi][1] - nm1);
            mrow[mi][0] = nm0; mrow[mi][1] = nm1;
#pragma unroll
            for (int n = 0; n < 4; ++n) {
                o[mi][n][0] *= cr0; o[mi][n][1] *= cr0;
                o[mi][n][2] *= cr1; o[mi][n][3] *= cr1;
            }
            osum[mi][0] *= cr0; osum[mi][1] *= cr0;
            osum[mi][2] *= cr1; osum[mi][3] *= cr1;
#pragma unroll
            for (int ni = 0; ni < NI; ++ni) {
                pu[mi][ni][0] = ex2_h2(pack_h2(c[mi][ni][0] - nm0, c[mi][ni][1] - nm0));
                pu[mi][ni][1] = ex2_h2(pack_h2(c[mi][ni][2] - nm1, c[mi][ni][3] - nm1));
            }
#pragma unroll
            for (int ni = NI; ni < 2 * NGRP; ++ni) {
                pu[mi][ni][0] = 0u; pu[mi][ni][1] = 0u;
            }
        }
        // ---- O += P V ; osum += P ones ------------------------------------
#pragma unroll
        for (int grp = 0; grp < NGRP; ++grp) {
            uint32_t vb[4][2], vb4[2];
            const uint32_t va = VsU[buf] + vOff + (uint32_t)(grp * 16 * LDKH * 2);
            ldsm_x4_t(vb[0][0], vb[0][1], vb[1][0], vb[1][1], va);
            ldsm_x4_t(vb[2][0], vb[2][1], vb[3][0], vb[3][1], va + 32);
            ldsm_x2_t(vb4[0], vb4[1], va + 64);
#pragma unroll
            for (int mi = 0; mi < 2; ++mi) {
                uint32_t pa[4] = { pu[mi][2 * grp][0],     pu[mi][2 * grp][1],
                                   pu[mi][2 * grp + 1][0], pu[mi][2 * grp + 1][1] };
#pragma unroll
                for (int n = 0; n < 4; ++n)
                    mma_f16(o[mi][n], pa, vb[n]);
                mma_f16(osum[mi], pa, vb4);
            }
        }
    };

    load_kv(0, 0);
    CP_COMMIT();
    for (int ch = 0; ch < 5; ++ch) {
        const int bu = ch & 1;
        load_kv(ch + 1, bu ^ 1);
        CP_COMMIT();
        CP_WAIT1();
        __syncthreads();
        compute(IC<8>{}, IC<4>{}, ch, bu);
        __syncthreads();
    }
    CP_WAIT0();
    __syncthreads();
    compute(IC<3>{}, IC<2>{}, 5, 1);

    if (active) {
        const int chk = h >> 1;
        const int gbase = (h & 1) * 4;
        const int qlane = lid & ~3;            // quad's t4==0 lane holds col 32
#pragma unroll
        for (int mi = 0; mi < 2; ++mi) {
            const float l0 = __shfl_sync(0xFFFFFFFF, osum[mi][0], qlane);
            const float l1 = __shfl_sync(0xFFFFFFFF, osum[mi][2], qlane);
            const float i0 = 1.f / l0;
            const float i1 = 1.f / l1;
            const int r0 = wm + mi * 16 + g;
            const int r1 = r0 + 8;
            if (r0 < NTOK) {
                size_t rg = (size_t)b * NTOK + r0;
                __half* op = out + ((size_t)chk * MROWS + rg) * 64 + 2 * t4;
                const int rx = (int)(rg & 7);
#pragma unroll
                for (int n = 0; n < 4; ++n)
                    *reinterpret_cast<uint32_t*>(op + (((gbase + n) ^ rx) << 3)) =
                        pack_h2(o[mi][n][0] * i0, o[mi][n][1] * i0);
            }
            if (r1 < NTOK) {
                size_t rg = (size_t)b * NTOK + r1;
                __half* op = out + ((size_t)chk * MROWS + rg) * 64 + 2 * t4;
                const int rx = (int)(rg & 7);
#pragma unroll
                for (int n = 0; n < 4; ++n)
                    *reinterpret_cast<uint32_t*>(op + (((gbase + n) ^ rx) << 3)) =
                        pack_h2(o[mi][n][2] * i1, o[mi][n][3] * i1);
            }
        }
    }
}

// ---------------- launch ------------------------------------------------------
extern "C" void kernel_launch(void* const* d_in, const int* in_sizes, int n_in,
                              void* d_out, int out_size)
{
    const float* x       = (const float*)d_in[0];
    const float* qkv_w   = (const float*)d_in[1];
    const float* qkv_b   = (const float*)d_in[2];
    const float* proj_w  = (const float*)d_in[3];
    const float* proj_b  = (const float*)d_in[4];
    const float* bt      = (const float*)d_in[5];
    const int*   ridx    = (const int*)d_in[6];
    float*       out     = (float*)d_out;

    void *p_qkv, *p_att, *p_bias, *p_xh, *p_wqt, *p_wpt;
    cudaGetSymbolAddress(&p_qkv,  g_qkv);
    cudaGetSymbolAddress(&p_att,  g_att);
    cudaGetSymbolAddress(&p_bias, g_biasH);
    cudaGetSymbolAddress(&p_xh,   g_xh);
    cudaGetSymbolAddress(&p_wqt,  g_wqt);
    cudaGetSymbolAddress(&p_wpt,  g_wpt);
    __half* qkvh = (__half*)p_qkv;
    __half* atth = (__half*)p_att;
    __half* bias = (__half*)p_bias;
    __half* xh   = (__half*)p_xh;
    __half* wqt  = (__half*)p_wqt;
    __half* wpt  = (__half*)p_wpt;

    cudaFuncSetAttribute(mma_gemm_h<false>,
                         cudaFuncAttributeMaxDynamicSharedMemorySize, GSM_TOT);
    cudaFuncSetAttribute(mma_gemm_h<true>,
                         cudaFuncAttributeMaxDynamicSharedMemorySize, GSM_TOT);

    // 0) fused prep
    prep_kernel<<<PREP_BLOCKS, 256>>>(x, qkv_w, proj_w, bt, ridx,
                                      xh, wqt, wpt, bias);

    // 1) QKV projection
    mma_gemm_h<false><<<dim3(QKVC / 128, MROWS / 128), 256, GSM_TOT>>>(
        xh, wqt, qkv_b, qkvh, QKVC);

    // 2) fp16 flash attention v2
    attn_f16_kernel<<<dim3(NHEADS, NWIN, 3), AT_THREADS>>>(qkvh, bias, atth);

    // 3) output projection
    mma_gemm_h<true><<<dim3(CDIM / 128, MROWS / 128), 256, GSM_TOT>>>(
        atth, wpt, proj_b, out, CDIM);
}

// round 15
// speedup vs baseline: 1.1558x; 1.0869x over previous
#include <cuda_runtime.h>
#include <cuda_fp16.h>
#include <cstdint>
#include <cstdio>

#define NTOK   343
#define NWIN   256
#define NHEADS 12
#define HDIM   32
#define CDIM   384
#define MROWS  (NWIN * NTOK)     // 87808
#define QKVC   (3 * CDIM)        // 1152
#define NPAD   384
#define KPAD   384

// ---------------- scratch (static device globals) ---------------------------
__device__ __half g_qkv[(size_t)MROWS * QKVC];     // normal layout (attn input; Q pre-scaled)
__device__ __half g_att[(size_t)MROWS * CDIM];     // chunk-major swizzled (proj A)
__device__ __half g_biasH[NHEADS * NPAD * KPAD];   // fragment-layout bias (log2e-scaled)
__device__ __half g_xh[(size_t)MROWS * CDIM];      // chunk-major swizzled (qkv A)
__device__ __half g_wqt[(size_t)QKVC * CDIM];      // chunk-major swizzled (qkv B)
__device__ __half g_wpt[(size_t)CDIM * CDIM];      // chunk-major swizzled (proj B)

template<int N> struct IC { static constexpr int value = N; };

// ======================= helpers ============================================
__device__ __forceinline__ uint32_t smem_u32(const void* p) {
    uint32_t a;
    asm("{ .reg .u64 t; cvta.to.shared.u64 t, %1; cvt.u32.u64 %0, t; }" : "=r"(a) : "l"(p));
    return a;
}
__device__ __forceinline__ uint32_t pack_h2(float lo, float hi) {
    uint32_t r;
    asm("cvt.rn.f16x2.f32 %0, %1, %2;" : "=r"(r) : "f"(hi), "f"(lo));
    return r;
}
__device__ __forceinline__ float ex2f(float x) {
    float r;
    asm("ex2.approx.f32 %0, %1;" : "=f"(r) : "f"(x));
    return r;
}
__device__ __forceinline__ void ldsm_x4(uint32_t& r0, uint32_t& r1, uint32_t& r2,
                                        uint32_t& r3, uint32_t addr) {
    asm volatile("ldmatrix.sync.aligned.m8n8.x4.shared.b16 {%0,%1,%2,%3}, [%4];"
                 : "=r"(r0), "=r"(r1), "=r"(r2), "=r"(r3) : "r"(addr));
}
__device__ __forceinline__ void ldsm_x4_t(uint32_t& r0, uint32_t& r1, uint32_t& r2,
                                          uint32_t& r3, uint32_t addr) {
    asm volatile("ldmatrix.sync.aligned.m8n8.x4.trans.shared.b16 {%0,%1,%2,%3}, [%4];"
                 : "=r"(r0), "=r"(r1), "=r"(r2), "=r"(r3) : "r"(addr));
}
__device__ __forceinline__ void ldsm_x2_t(uint32_t& r0, uint32_t& r1, uint32_t addr) {
    asm volatile("ldmatrix.sync.aligned.m8n8.x2.trans.shared.b16 {%0,%1}, [%2];"
                 : "=r"(r0), "=r"(r1) : "r"(addr));
}
#define CP_ASYNC16P(dst, src, n) \
    asm volatile("cp.async.cg.shared.global [%0], [%1], 16, %2;" :: "r"(dst), "l"(src), "r"(n))
#define CP_COMMIT() asm volatile("cp.async.commit_group;" ::: "memory")
#define CP_WAIT1()  asm volatile("cp.async.wait_group 1;" ::: "memory")
#define CP_WAIT0()  asm volatile("cp.async.wait_group 0;" ::: "memory")

#define MBARRIER_INIT(mb, cnt) \
    asm volatile("mbarrier.init.shared.b64 [%0], %1;" :: "r"((uint32_t)(mb)), "r"((uint32_t)(cnt)) : "memory")
#define MBARRIER_EXPECT_TX(mb, bytes) \
    asm volatile("mbarrier.arrive.expect_tx.shared.b64 _, [%0], %1;" :: "r"((uint32_t)(mb)), "r"((uint32_t)(bytes)) : "memory")
#define CP_BULK(dst, src, bytes, mb) \
    asm volatile("cp.async.bulk.shared::cluster.global.mbarrier::complete_tx::bytes [%0], [%1], %2, [%3];" \
                 :: "r"((uint32_t)(dst)), "l"(src), "r"((uint32_t)(bytes)), "r"((uint32_t)(mb)) : "memory")
#define MBARRIER_WAIT_PARITY(mb, ph) do {                                         \
    uint32_t _mb = (uint32_t)(mb); uint32_t _p = (uint32_t)(ph); uint32_t _done;  \
    asm volatile("{\n\t.reg .pred p;\n\t"                                         \
        "mbarrier.try_wait.parity.acquire.cta.shared::cta.b64 p, [%1], %2;\n\t"   \
        "selp.b32 %0, 1, 0, p;\n\t}" : "=r"(_done) : "r"(_mb), "r"(_p) : "memory"); \
    if (!_done) {                                                                 \
        asm volatile("{\n\t.reg .pred P1;\n\t"                                    \
            "WL_%=:\n\t"                                                          \
            "mbarrier.try_wait.parity.acquire.cta.shared::cta.b64 P1, [%0], %1, 0x989680;\n\t" \
            "@P1 bra.uni WD_%=;\n\t"                                              \
            "bra.uni WL_%=;\n\t"                                                  \
            "WD_%=:\n\t}" :: "r"(_mb), "r"(_p) : "memory");                       \
    }                                                                             \
} while (0)

__device__ __forceinline__ void mma_f16(float* c, const uint32_t* a, const uint32_t* b) {
    asm volatile(
        "mma.sync.aligned.m16n8k16.row.col.f32.f16.f16.f32 "
        "{%0,%1,%2,%3}, {%4,%5,%6,%7}, {%8,%9}, {%0,%1,%2,%3};"
        : "+f"(c[0]), "+f"(c[1]), "+f"(c[2]), "+f"(c[3])
        : "r"(a[0]), "r"(a[1]), "r"(a[2]), "r"(a[3]), "r"(b[0]), "r"(b[1]));
}

// ======================= fused prep kernel ==================================
#define NBX  16464
#define NBB  6912
#define NBTQ 432
#define NBTP 144
#define PREP_BLOCKS (NBX + NBB + NBTQ + NBTP)
#define LOG2E 1.4426950408889634f

__global__ __launch_bounds__(256) void prep_kernel(
    const float* __restrict__ x, const float* __restrict__ qkv_w,
    const float* __restrict__ proj_w, const float* __restrict__ bt,
    const int* __restrict__ ridx,
    __half* __restrict__ xh, __half* __restrict__ wqt,
    __half* __restrict__ wpt, __half* __restrict__ bf)
{
    __shared__ float t[32][33];
    const int bid = blockIdx.x;
    const int tid = threadIdx.x;

    if (bid < NBX) {
        size_t e = ((size_t)bid * 256 + tid) * 8;
        int row = (int)(e / CDIM);
        int hcf = (int)(e % CDIM);
        int c   = hcf >> 6;
        int grp = (hcf & 63) >> 3;
        float4 v0 = *reinterpret_cast<const float4*>(x + e);
        float4 v1 = *reinterpret_cast<const float4*>(x + e + 4);
        uint4 o;
        o.x = pack_h2(v0.x, v0.y); o.y = pack_h2(v0.z, v0.w);
        o.z = pack_h2(v1.x, v1.y); o.w = pack_h2(v1.z, v1.w);
        size_t dst = ((size_t)c * MROWS + row) * 64 + ((grp ^ (row & 7)) << 3);
        *reinterpret_cast<uint4*>(xh + dst) = o;
        return;
    }
    if (bid < NBX + NBB) {
        int idx = (bid - NBX) * 256 + tid;
        int h   = idx / (NPAD * KPAD);
        int rem = idx - h * NPAD * KPAD;
        int r   = rem / KPAD;
        int k   = rem - r * KPAD;
        float v;
        if (k >= NTOK)      v = -60000.f;
        else if (r >= NTOK) v = 0.f;
        else                v = bt[ridx[r * NTOK + k] * NHEADS + h] * LOG2E;
        // fragment layout: [h][r][chunk][t4][ni][e]
        int chunk = k >> 6, kc = k & 63;
        int ni = kc >> 3, t4b = (kc & 7) >> 1, e = kc & 1;
        size_t dst = (((size_t)h * NPAD + r) * 6 + chunk) * 64
                     + t4b * 16 + ni * 2 + e;
        bf[dst] = __float2half(v);
        return;
    }
    const int tx = tid & 31, ty = tid >> 5;
    const float* W; __half* Wt; int Nw, bx, by;
    if (bid < NBX + NBB + NBTQ) {
        int bb = bid - NBX - NBB;
        W = qkv_w; Wt = wqt; Nw = QKVC;
        bx = bb % (QKVC / 32); by = bb / (QKVC / 32);
    } else {
        int bb = bid - NBX - NBB - NBTQ;
        W = proj_w; Wt = wpt; Nw = CDIM;
        bx = bb % (CDIM / 32); by = bb / (CDIM / 32);
    }
    int n0 = bx * 32, k0 = by * 32;
#pragma unroll
    for (int s = 0; s < 4; ++s) {
        int k = k0 + ty + s * 8;
        t[ty + s * 8][tx] = W[(size_t)k * Nw + n0 + tx];
    }
    __syncthreads();
#pragma unroll
    for (int s = 0; s < 4; ++s) {
        int n = n0 + ty + s * 8;
        int k = k0 + tx;
        int c = k >> 6, hc = k & 63;
        size_t dst = ((size_t)c * Nw + n) * 64
                     + ((((hc >> 3) ^ (n & 7))) << 3) + (hc & 7);
        Wt[dst] = __float2half(t[tx][ty + s * 8]);
    }
}

// ======================= fp16 mma GEMM (R13 + col-scale epilogue) ===========
#define GNCHUNK  6
#define ASTG_B   16384
#define STG_B    (2 * ASTG_B)
#define GSM_TOT  (3 * STG_B + 24)
#define QSCALE   (0.17677669529663687f * LOG2E)   // applied to Q cols in fp32

template<bool OUT_FLOAT, bool SCALE_Q>
__global__ __launch_bounds__(256, 2) void mma_gemm_h(
    const __half* __restrict__ A, const __half* __restrict__ Wt,
    const float* __restrict__ bias, void* __restrict__ Cout, int Ntot)
{
    extern __shared__ __half smh[];
    const uint32_t sbase = smem_u32(smh);
    uint32_t sAu[3], sBu[3], mb[3];
#pragma unroll
    for (int s = 0; s < 3; ++s) {
        sAu[s] = sbase + s * STG_B;
        sBu[s] = sbase + s * STG_B + ASTG_B;
        mb[s]  = sbase + 3 * STG_B + s * 8;
    }

    const int tid = threadIdx.x;
    const int wid = tid >> 5, lid = tid & 31;
    const int g = lid >> 2, t4 = lid & 3;
    const int grp4 = lid >> 3;
    const int x7 = lid & 7;
    const int wm = (wid & 1) * 64;
    const int wn = (wid >> 1) * 32;
    const int bm = blockIdx.y * 128;
    const int bn = blockIdx.x * 128;

    const uint32_t aRow = (uint32_t)(wm + (grp4 & 1) * 8 + x7) * 128;
    const int cA = grp4 >> 1;
    const uint32_t bRow = (uint32_t)(wn + (grp4 >> 1) * 8 + x7) * 128;
    const int cB = grp4 & 1;

    if (tid == 0) {
        MBARRIER_INIT(mb[0], 1); MBARRIER_INIT(mb[1], 1); MBARRIER_INIT(mb[2], 1);
    }
    __syncthreads();
    int ph[3] = {0, 0, 0};

    float acc[4][4][4];
#pragma unroll
    for (int i = 0; i < 4; ++i)
#pragma unroll
        for (int j = 0; j < 4; ++j)
#pragma unroll
            for (int q = 0; q < 4; ++q) acc[i][j][q] = 0.f;

    auto issue = [&](int c, int buf) {
        if (tid == 0) {
            MBARRIER_EXPECT_TX(mb[buf], (uint32_t)STG_B);
            CP_BULK(sAu[buf], A  + ((size_t)c * MROWS + bm) * 64, (uint32_t)ASTG_B, mb[buf]);
            CP_BULK(sBu[buf], Wt + ((size_t)c * Ntot  + bn) * 64, (uint32_t)ASTG_B, mb[buf]);
        }
    };

    issue(0, 0);
    issue(1, 1);
    for (int c = 0; c < GNCHUNK; ++c) {
        const int buf = c % 3;
        MBARRIER_WAIT_PARITY(mb[buf], ph[buf]);
        ph[buf] ^= 1;

#pragma unroll
        for (int ks = 0; ks < 4; ++ks) {
            uint32_t af[4][4], bf[4][2];
            const uint32_t aSw = (uint32_t)(((ks * 2 + cA) ^ x7) << 4);
            const uint32_t bSw = (uint32_t)(((ks * 2 + cB) ^ x7) << 4);
#pragma unroll
            for (int mi = 0; mi < 4; ++mi)
                ldsm_x4(af[mi][0], af[mi][1], af[mi][2], af[mi][3],
                        sAu[buf] + aRow + (uint32_t)(mi * 2048) + aSw);
            ldsm_x4(bf[0][0], bf[0][1], bf[1][0], bf[1][1], sBu[buf] + bRow + bSw);
            ldsm_x4(bf[2][0], bf[2][1], bf[3][0], bf[3][1], sBu[buf] + bRow + 2048 + bSw);
#pragma unroll
            for (int mi = 0; mi < 4; ++mi)
#pragma unroll
                for (int ni = 0; ni < 4; ++ni)
                    mma_f16(acc[mi][ni], af[mi], bf[ni]);
        }
        __syncthreads();
        if (c + 2 < GNCHUNK) issue(c + 2, (c + 2) % 3);
    }

#pragma unroll
    for (int mi = 0; mi < 4; ++mi) {
#pragma unroll
        for (int ni = 0; ni < 4; ++ni) {
            const int row = bm + wm + mi * 16 + g;
            const int col = bn + wn + ni * 8 + t4 * 2;
            const float b0 = __ldg(&bias[col]), b1 = __ldg(&bias[col + 1]);
            float v00 = acc[mi][ni][0] + b0, v01 = acc[mi][ni][1] + b1;
            float v10 = acc[mi][ni][2] + b0, v11 = acc[mi][ni][3] + b1;
            if (SCALE_Q && col < CDIM) {          // Q region: fold softmax scale (fp32)
                v00 *= QSCALE; v01 *= QSCALE;
                v10 *= QSCALE; v11 *= QSCALE;
            }
            if (OUT_FLOAT) {
                float* C = reinterpret_cast<float*>(Cout);
                *reinterpret_cast<float2*>(&C[(size_t)row * Ntot + col])       = make_float2(v00, v01);
                *reinterpret_cast<float2*>(&C[(size_t)(row + 8) * Ntot + col]) = make_float2(v10, v11);
            } else {
                __half* C = reinterpret_cast<__half*>(Cout);
                *reinterpret_cast<uint32_t*>(&C[(size_t)row * Ntot + col])       = pack_h2(v00, v01);
                *reinterpret_cast<uint32_t*>(&C[(size_t)(row + 8) * Ntot + col]) = pack_h2(v10, v11);
            }
        }
    }
}

// ======================= fp16 flash attention v3 ============================
// - Q pre-scaled in QKV GEMM (fp32) -> raw fragment loads here
// - S accumulators initialized from fragment-layout bias (LDG.128)
// - exp2 in fp32, packed to fp16 P fragments
// - row-sum l via ones-column in V pad space (fp32 mma accumulation)
#define AT_THREADS 128
#define LDKH 40

__global__ __launch_bounds__(AT_THREADS, 1) void attn_f16_kernel(
    const __half* __restrict__ qkv, const __half* __restrict__ biasP,
    __half* __restrict__ out)
{
    __shared__ __half Ks[2][64 * LDKH];
    __shared__ __half Vs[2][64 * LDKH];
    const int h   = blockIdx.x;
    const int b   = blockIdx.y;
    const int tid = threadIdx.x;
    const int wid = tid >> 5, lid = tid & 31;
    const int g = lid >> 2, t4 = lid & 3;
    const int grp4 = lid >> 3;
    const int wm = blockIdx.z * 128 + wid * 32;
    const bool active = wm < NTOK;
    const __half* base = qkv + (size_t)b * NTOK * QKVC;
    const uint32_t KsU[2] = { smem_u32(Ks[0]), smem_u32(Ks[1]) };
    const uint32_t VsU[2] = { smem_u32(Vs[0]), smem_u32(Vs[1]) };

    const uint32_t kOff = (uint32_t)(((grp4 >> 1) * 8 + (lid & 7)) * LDKH
                                     + (grp4 & 1) * 8) * 2;
    const uint32_t vOff = (uint32_t)((lid & 15) * LDKH + (lid >> 4) * 8) * 2;

    // ones-column init in V pad space (col 32 = 1.0, cols 33..39 = 0), both bufs
    {
        int buf = tid >> 6, row = tid & 63;
        uint4 ones = make_uint4(0x00003C00u, 0u, 0u, 0u);
        *reinterpret_cast<uint4*>(&Vs[buf][row * LDKH + 32]) = ones;
    }

    // ---- Q a-frags from global (already scaled in GEMM) -------------------
    uint32_t qa[2][2][4];
#pragma unroll
    for (int mi = 0; mi < 2; ++mi) {
        const int r0 = wm + mi * 16 + g, r1 = r0 + 8;
        const __half* q0 = base + (size_t)r0 * QKVC + h * HDIM;
        const __half* q1 = base + (size_t)r1 * QKVC + h * HDIM;
#pragma unroll
        for (int ks = 0; ks < 2; ++ks) {
            const int k2 = ks * 16 + 2 * t4;
            qa[mi][ks][0] = (r0 < NTOK) ? *reinterpret_cast<const uint32_t*>(q0 + k2) : 0u;
            qa[mi][ks][1] = (r1 < NTOK) ? *reinterpret_cast<const uint32_t*>(q1 + k2) : 0u;
            qa[mi][ks][2] = (r0 < NTOK) ? *reinterpret_cast<const uint32_t*>(q0 + k2 + 8) : 0u;
            qa[mi][ks][3] = (r1 < NTOK) ? *reinterpret_cast<const uint32_t*>(q1 + k2 + 8) : 0u;
        }
    }

    float o[2][4][4];
    float osum[2][4];
#pragma unroll
    for (int mi = 0; mi < 2; ++mi) {
#pragma unroll
        for (int n = 0; n < 4; ++n)
#pragma unroll
            for (int q = 0; q < 4; ++q) o[mi][n][q] = 0.f;
#pragma unroll
        for (int q = 0; q < 4; ++q) osum[mi][q] = 0.f;
    }
    float mrow[2][2] = {{-1e30f, -1e30f}, {-1e30f, -1e30f}};

    auto load_kv = [&](int ch, int buf) {
        const int j0 = ch * 64;
#pragma unroll
        for (int i = 0; i < 2; ++i) {
            int f = tid + i * 128;
            int row = f >> 2, c16 = (f & 3) * 8;
            int kr = j0 + row;
            uint32_t pred = (kr < NTOK) ? 16u : 0u;
            const __half* rp = base + (size_t)kr * QKVC + h * HDIM + c16;
            CP_ASYNC16P(KsU[buf] + (uint32_t)(row * LDKH + c16) * 2, rp + CDIM, pred);
            CP_ASYNC16P(VsU[buf] + (uint32_t)(row * LDKH + c16) * 2, rp + 2 * CDIM, pred);
        }
    };

    auto compute = [&](auto NIc, auto NGRPc, int ch, int buf) {
        constexpr int NI   = decltype(NIc)::value;
        constexpr int NGRP = decltype(NGRPc)::value;
        if (!active) return;

        // ---- S accumulators from fragment-layout bias (LDG.128) -----------
        float c[2][8][4];
#pragma unroll
        for (int mi = 0; mi < 2; ++mi) {
            const int r0 = wm + mi * 16 + g;
            const uint32_t* b0w = reinterpret_cast<const uint32_t*>(
                biasP + (((size_t)h * NPAD + r0) * 6 + ch) * 64 + t4 * 16);
            const uint32_t* b1w = reinterpret_cast<const uint32_t*>(
                biasP + (((size_t)h * NPAD + r0 + 8) * 6 + ch) * 64 + t4 * 16);
            uint32_t b0[8], b1[8];
            *reinterpret_cast<uint4*>(&b0[0]) = *reinterpret_cast<const uint4*>(b0w);
            *reinterpret_cast<uint4*>(&b1[0]) = *reinterpret_cast<const uint4*>(b1w);
            if (NI > 4) {
                *reinterpret_cast<uint4*>(&b0[4]) = *reinterpret_cast<const uint4*>(b0w + 4);
                *reinterpret_cast<uint4*>(&b1[4]) = *reinterpret_cast<const uint4*>(b1w + 4);
            }
#pragma unroll
            for (int ni = 0; ni < NI; ++ni) {
                float2 f0 = __half22float2(*reinterpret_cast<const __half2*>(&b0[ni]));
                float2 f1 = __half22float2(*reinterpret_cast<const __half2*>(&b1[ni]));
                c[mi][ni][0] = f0.x; c[mi][ni][1] = f0.y;
                c[mi][ni][2] = f1.x; c[mi][ni][3] = f1.y;
            }
        }
        // ---- S += Q K^T ---------------------------------------------------
#pragma unroll
        for (int ks = 0; ks < 2; ++ks) {
            uint32_t kb[8][2];
#pragma unroll
            for (int p = 0; p < (NI + 1) / 2; ++p)
                ldsm_x4(kb[2*p][0], kb[2*p][1], kb[2*p+1][0], kb[2*p+1][1],
                        KsU[buf] + kOff + (uint32_t)(p * 16 * LDKH * 2 + ks * 32));
#pragma unroll
            for (int mi = 0; mi < 2; ++mi)
#pragma unroll
                for (int ni = 0; ni < NI; ++ni)
                    mma_f16(c[mi][ni], qa[mi][ks], kb[ni]);
        }
        // ---- online softmax: exp2 in fp32, pack to fp16 P -----------------
        uint32_t pu[2][2 * NGRP][2];
#pragma unroll
        for (int mi = 0; mi < 2; ++mi) {
            float mx0 = c[mi][0][0], mx1 = c[mi][0][2];
#pragma unroll
            for (int ni = 0; ni < NI; ++ni) {
                mx0 = fmaxf(mx0, fmaxf(c[mi][ni][0], c[mi][ni][1]));
                mx1 = fmaxf(mx1, fmaxf(c[mi][ni][2], c[mi][ni][3]));
            }
            mx0 = fmaxf(mx0, __shfl_xor_sync(0xFFFFFFFF, mx0, 1));
            mx0 = fmaxf(mx0, __shfl_xor_sync(0xFFFFFFFF, mx0, 2));
            mx1 = fmaxf(mx1, __shfl_xor_sync(0xFFFFFFFF, mx1, 1));
            mx1 = fmaxf(mx1, __shfl_xor_sync(0xFFFFFFFF, mx1, 2));
            float nm0 = fmaxf(mrow[mi][0], mx0);
            float nm1 = fmaxf(mrow[mi][1], mx1);
            float cr0 = ex2f(mrow[mi][0] - nm0);
            float cr1 = ex2f(mrow[mi][1] - nm1);
            mrow[mi][0] = nm0; mrow[mi][1] = nm1;
#pragma unroll
            for (int n = 0; n < 4; ++n) {
                o[mi][n][0] *= cr0; o[mi][n][1] *= cr0;
                o[mi][n][2] *= cr1; o[mi][n][3] *= cr1;
            }
            osum[mi][0] *= cr0; osum[mi][1] *= cr0;
            osum[mi][2] *= cr1; osum[mi][3] *= cr1;
#pragma unroll
            for (int ni = 0; ni < NI; ++ni) {
                float p0 = ex2f(c[mi][ni][0] - nm0);
                float p1 = ex2f(c[mi][ni][1] - nm0);
                float p2 = ex2f(c[mi][ni][2] - nm1);
                float p3 = ex2f(c[mi][ni][3] - nm1);
                pu[mi][ni][0] = pack_h2(p0, p1);
                pu[mi][ni][1] = pack_h2(p2, p3);
            }
#pragma unroll
            for (int ni = NI; ni < 2 * NGRP; ++ni) {
                pu[mi][ni][0] = 0u; pu[mi][ni][1] = 0u;
            }
        }
        // ---- O += P V ; osum += P ones ------------------------------------
#pragma unroll
        for (int grp = 0; grp < NGRP; ++grp) {
            uint32_t vb[4][2], vb4[2];
            const uint32_t va = VsU[buf] + vOff + (uint32_t)(grp * 16 * LDKH * 2);
            ldsm_x4_t(vb[0][0], vb[0][1], vb[1][0], vb[1][1], va);
            ldsm_x4_t(vb[2][0], vb[2][1], vb[3][0], vb[3][1], va + 32);
            ldsm_x2_t(vb4[0], vb4[1], va + 64);
#pragma unroll
            for (int mi = 0; mi < 2; ++mi) {
                uint32_t pa[4] = { pu[mi][2 * grp][0],     pu[mi][2 * grp][1],
                                   pu[mi][2 * grp + 1][0], pu[mi][2 * grp + 1][1] };
#pragma unroll
                for (int n = 0; n < 4; ++n)
                    mma_f16(o[mi][n], pa, vb[n]);
                mma_f16(osum[mi], pa, vb4);
            }
        }
    };

    load_kv(0, 0);
    CP_COMMIT();
    for (int ch = 0; ch < 5; ++ch) {
        const int bu = ch & 1;
        load_kv(ch + 1, bu ^ 1);
        CP_COMMIT();
        CP_WAIT1();
        __syncthreads();
        compute(IC<8>{}, IC<4>{}, ch, bu);
        __syncthreads();
    }
    CP_WAIT0();
    __syncthreads();
    compute(IC<3>{}, IC<2>{}, 5, 1);

    if (active) {
        const int chk = h >> 1;
        const int gbase = (h & 1) * 4;
        const int qlane = lid & ~3;
#pragma unroll
        for (int mi = 0; mi < 2; ++mi) {
            const float l0 = __shfl_sync(0xFFFFFFFF, osum[mi][0], qlane);
            const float l1 = __shfl_sync(0xFFFFFFFF, osum[mi][2], qlane);
            const float i0 = 1.f / l0;
            const float i1 = 1.f / l1;
            const int r0 = wm + mi * 16 + g;
            const int r1 = r0 + 8;
            if (r0 < NTOK) {
                size_t rg = (size_t)b * NTOK + r0;
                __half* op = out + ((size_t)chk * MROWS + rg) * 64 + 2 * t4;
                const int rx = (int)(rg & 7);
#pragma unroll
                for (int n = 0; n < 4; ++n)
                    *reinterpret_cast<uint32_t*>(op + (((gbase + n) ^ rx) << 3)) =
                        pack_h2(o[mi][n][0] * i0, o[mi][n][1] * i0);
            }
            if (r1 < NTOK) {
                size_t rg = (size_t)b * NTOK + r1;
                __half* op = out + ((size_t)chk * MROWS + rg) * 64 + 2 * t4;
                const int rx = (int)(rg & 7);
#pragma unroll
                for (int n = 0; n < 4; ++n)
                    *reinterpret_cast<uint32_t*>(op + (((gbase + n) ^ rx) << 3)) =
                        pack_h2(o[mi][n][2] * i1, o[mi][n][3] * i1);
            }
        }
    }
}

// ---------------- launch ------------------------------------------------------
extern "C" void kernel_launch(void* const* d_in, const int* in_sizes, int n_in,
                              void* d_out, int out_size)
{
    const float* x       = (const float*)d_in[0];
    const float* qkv_w   = (const float*)d_in[1];
    const float* qkv_b   = (const float*)d_in[2];
    const float* proj_w  = (const float*)d_in[3];
    const float* proj_b  = (const float*)d_in[4];
    const float* bt      = (const float*)d_in[5];
    const int*   ridx    = (const int*)d_in[6];
    float*       out     = (float*)d_out;

    void *p_qkv, *p_att, *p_bias, *p_xh, *p_wqt, *p_wpt;
    cudaGetSymbolAddress(&p_qkv,  g_qkv);
    cudaGetSymbolAddress(&p_att,  g_att);
    cudaGetSymbolAddress(&p_bias, g_biasH);
    cudaGetSymbolAddress(&p_xh,   g_xh);
    cudaGetSymbolAddress(&p_wqt,  g_wqt);
    cudaGetSymbolAddress(&p_wpt,  g_wpt);
    __half* qkvh = (__half*)p_qkv;
    __half* atth = (__half*)p_att;
    __half* bias = (__half*)p_bias;
    __half* xh   = (__half*)p_xh;
    __half* wqt  = (__half*)p_wqt;
    __half* wpt  = (__half*)p_wpt;

    cudaFuncSetAttribute((const void*)&mma_gemm_h<false, true>,
                         cudaFuncAttributeMaxDynamicSharedMemorySize, GSM_TOT);
    cudaFuncSetAttribute((const void*)&mma_gemm_h<true, false>,
                         cudaFuncAttributeMaxDynamicSharedMemorySize, GSM_TOT);

    // 0) fused prep
    prep_kernel<<<PREP_BLOCKS, 256>>>(x, qkv_w, proj_w, bt, ridx,
                                      xh, wqt, wpt, bias);

    // 1) QKV projection (Q columns scaled in fp32 epilogue)
    mma_gemm_h<false, true><<<dim3(QKVC / 128, MROWS / 128), 256, GSM_TOT>>>(
        xh, wqt, qkv_b, qkvh, QKVC);

    // 2) fp16 flash attention v3
    attn_f16_kernel<<<dim3(NHEADS, NWIN, 3), AT_THREADS>>>(qkvh, bias, atth);

    // 3) output projection
    mma_gemm_h<true, false><<<dim3(CDIM / 128, MROWS / 128), 256, GSM_TOT>>>(
        atth, wpt, proj_b, out, CDIM);
}